// round 15
// baseline (speedup 1.0000x reference)
#include <cuda_runtime.h>
#include <cuda_fp16.h>
#include <cstdint>

// Problem constants
#define Bv   2
#define Sv   2048
#define Dv   1024
#define Hv   16
#define DKv  64
#define Fv   4096
#define Mv   (Bv * Sv)      // 4096 rows
#define QS   3072           // qkv row stride (halves)
#define LN_EPS 1e-6f
#define QSCALE_F (0.125f * 1.4426950408889634f)

// fp16 k-permutation: within each 16-group, pair p=(k&15)>>1 stored at slot
// perm8(p) = p<4 ? 2p : 2p-7. Slot order of a 16-group:
//   [l0,l1, l8,l9, l2,l3, l10,l11, l4,l5, l12,l13, l6,l7, l14,l15]

// ---------------------------------------------------------------------------
// Scratch
// ---------------------------------------------------------------------------
__device__ __half g_qkv [(size_t)Mv * QS];            // q|k|v fp16, d perm16 (q pre-scaled)
__device__ __half g_xr  [(size_t)Mv * Dv];            // x fp16, perm16
__device__ __half g_attn[(size_t)Mv * Dv];            // flash out fp16, perm16
__device__ __half g_h   [(size_t)Mv * Dv];            // LN1 out fp16, perm16
__device__ __half g_ff1 [(size_t)Mv * Fv];            // ff1 out fp16, perm16
__device__ __half g_vt  [(size_t)Bv * Dv * Sv];       // V transposed [b][d][jperm]
__device__ __half g_tmp [(size_t)Mv * Dv];            // wo out fp16 STANDARD
__device__ __half g_tmp2[(size_t)Mv * Dv];            // ff2 out fp16 STANDARD
__device__ __half g_w   [(size_t)12 * 1024 * 1024];   // fp16 weights, k perm16
__device__ float  g_bqkv[QS];

// ---------------------------------------------------------------------------
// Helpers
// ---------------------------------------------------------------------------
__device__ __forceinline__ uint32_t smem_u32(const void* p) {
    uint32_t a;
    asm("{ .reg .u64 t; cvta.to.shared.u64 t, %1; cvt.u32.u64 %0, t; }"
        : "=r"(a) : "l"(p));
    return a;
}
__device__ __forceinline__ int perm8i(int t) { return (t < 4) ? 2 * t : 2 * t - 7; }
__device__ __forceinline__ int kperm16(int k) {
    return (k & ~15) | (2 * perm8i((k & 15) >> 1) + (k & 1));
}
__device__ __forceinline__ uint32_t h2pack(float x, float y) {
    __half2 h = __floats2half2_rn(x, y);
    return *(uint32_t*)&h;
}
__device__ __forceinline__ void mma_f16(
    float* d, uint32_t a0, uint32_t a1, uint32_t a2, uint32_t a3,
    uint32_t b0, uint32_t b1)
{
    asm volatile(
        "mma.sync.aligned.m16n8k16.row.col.f32.f16.f16.f32 "
        "{%0,%1,%2,%3}, {%4,%5,%6,%7}, {%8,%9}, {%0,%1,%2,%3};"
        : "+f"(d[0]), "+f"(d[1]), "+f"(d[2]), "+f"(d[3])
        : "r"(a0), "r"(a1), "r"(a2), "r"(a3), "r"(b0), "r"(b1));
}

// ---------------------------------------------------------------------------
// Mega prep: ONE launch, all weight transposes + x rounding + bias pack.
// ---------------------------------------------------------------------------
#define MEGA_BLOCKS 13315

__device__ __forceinline__ void transpose_tile_f16(
    const float* __restrict__ W, __half* __restrict__ WT,
    int K, int N, int k0, int n0, int tx, int ty0)
{
    __shared__ float t[32][33];
#pragma unroll
    for (int i = 0; i < 4; ++i) {
        const int ty = ty0 + i * 8;
        t[ty][tx] = W[(size_t)(k0 + ty) * N + n0 + tx];
    }
    __syncthreads();
    const int txs = kperm16(tx);
#pragma unroll
    for (int i = 0; i < 4; ++i) {
        const int ty = ty0 + i * 8;
        WT[(size_t)(n0 + ty) * K + k0 + txs] = __float2half_rn(t[tx][ty]);
    }
}

__global__ void __launch_bounds__(256) mega_prep(
    const float* __restrict__ wq, const float* __restrict__ wk,
    const float* __restrict__ wv, const float* __restrict__ wo,
    const float* __restrict__ w1, const float* __restrict__ w2,
    const float* __restrict__ x,
    const float* __restrict__ bq, const float* __restrict__ bk,
    const float* __restrict__ bv,
    __half* __restrict__ wdst, __half* __restrict__ xr,
    float* __restrict__ bias)
{
    const int idx = blockIdx.x;
    const int tid = threadIdx.x;

    if (idx < 12288) {
        const int tx  = tid & 31;
        const int ty0 = tid >> 5;
        const float* W; __half* WT; int K, N, kt, nt;
        if (idx < 4096) {
            const int m = idx >> 10, tile = idx & 1023;
            const float* srcs[4] = { wq, wk, wv, wo };
            W = srcs[m]; WT = wdst + (size_t)m * Dv * Dv;
            K = Dv; N = Dv; kt = tile >> 5; nt = tile & 31;
        } else if (idx < 8192) {
            const int tile = idx - 4096;
            W = w1; WT = wdst + (size_t)4 * 1024 * 1024;
            K = Dv; N = Fv; kt = tile & 31; nt = tile >> 5;
        } else {
            const int tile = idx - 8192;
            W = w2; WT = wdst + (size_t)8 * 1024 * 1024;
            K = Fv; N = Dv; kt = tile >> 5; nt = tile & 31;
        }
        transpose_tile_f16(W, WT, K, N, kt * 32, nt * 32, tx, ty0);
    } else if (idx < 13312) {
        const int blk = idx - 12288;
        const size_t base = ((size_t)blk * 256 + tid) * 16;
        const float4 a = *(const float4*)(x + base);
        const float4 b = *(const float4*)(x + base + 4);
        const float4 cc = *(const float4*)(x + base + 8);
        const float4 d = *(const float4*)(x + base + 12);
        uint4 u0, u1;
        u0.x = h2pack(a.x, a.y);   u0.y = h2pack(cc.x, cc.y);
        u0.z = h2pack(a.z, a.w);   u0.w = h2pack(cc.z, cc.w);
        u1.x = h2pack(b.x, b.y);   u1.y = h2pack(d.x, d.y);
        u1.z = h2pack(b.z, b.w);   u1.w = h2pack(d.z, d.w);
        *(uint4*)(xr + base)     = u0;
        *(uint4*)(xr + base + 8) = u1;
    } else {
        const int j = idx - 13312;   // 0..2
        const float* src = (j == 0) ? bq : (j == 1) ? bk : bv;
        ((float4*)bias)[j * 256 + tid] = ((const float4*)src)[tid];
    }
}

// ---------------------------------------------------------------------------
// V transpose: qkv V-part [token][dperm] -> vt[b][dperm][jperm]
// ---------------------------------------------------------------------------
__global__ void __launch_bounds__(256) transpose_v(
    const __half* __restrict__ qkv, __half* __restrict__ vt)
{
    __shared__ __half t[64][66];
    const int j0 = blockIdx.x * 64, d0 = blockIdx.y * 64, b = blockIdx.z;
    const int tx = threadIdx.x, ty = threadIdx.y;   // 32 x 8

#pragma unroll
    for (int i = 0; i < 8; ++i) {
        const int j = ty + i * 8;
        const __half2 v = *(const __half2*)(
            qkv + (size_t)(b * Sv + j0 + j) * QS + 2048 + d0 + 2 * tx);
        t[2 * tx][j]     = __low2half(v);
        t[2 * tx + 1][j] = __high2half(v);
    }
    __syncthreads();
    const int js0 = kperm16(tx);
    const int js1 = kperm16(tx + 32);
#pragma unroll
    for (int i = 0; i < 8; ++i) {
        const int d = ty + i * 8;
        __half* dst = vt + ((size_t)b * Dv + d0 + d) * Sv + j0;
        dst[js0] = t[d][tx];
        dst[js1] = t[d][tx + 32];
    }
}

// ---------------------------------------------------------------------------
// fp16 tensor-core GEMM: 256 threads = 8 warps (4x2 grid of 64x64) ->
// 256x128 CTA tile (A L2-traffic halved vs 128x128). BK=64, 2-stage
// cp.async with the PROVEN wait_group(0) single-barrier pipeline.
// ---------------------------------------------------------------------------
#define GBK 64
#define GSTR 80
#define GSM_A (256 * GSTR)           // 20480 halves
#define GSM_B (128 * GSTR)           // 10240 halves
#define GSM_STG (GSM_A + GSM_B)      // 30720 halves (60KB)
#define GSMEM_BYTES (2 * GSM_STG * 2)   // 122880 (120KB) -> 1 CTA/SM

template <bool RELU, bool PERMOUT, bool QSC>
__global__ void __launch_bounds__(256)
gemm_h(int K, int N, const __half* __restrict__ A,
       const __half* __restrict__ W, const float* __restrict__ bias,
       __half* __restrict__ C)
{
    extern __shared__ __half smh[];
    const int m0 = blockIdx.y * 256;
    const int n0 = blockIdx.x * 128;
    const int tid  = threadIdx.x;
    const int lane = tid & 31;
    const int wid  = tid >> 5;
    const int wm = (wid >> 1) * 64;   // 0/64/128/192
    const int wn = (wid & 1) * 64;    // 0/64

    const __half* Ab = A + (size_t)m0 * K;
    const __half* Bb = W + (size_t)n0 * K;
    const int nk = K / GBK;

    float acc[4][8][4] = {};

    auto load_stage = [&](int buf, int kt) {
        __half* stg = smh + (size_t)buf * GSM_STG;
        const uint32_t ua = smem_u32(stg);
        const uint32_t ub = smem_u32(stg + GSM_A);
#pragma unroll
        for (int i = 0; i < 8; ++i) {          // A: 256 rows x 64 halves
            const int s   = tid + i * 256;     // 0..2047
            const int row = s >> 3;
            const int f   = s & 7;
            const __half* ga = Ab + (size_t)row * K + kt * GBK + f * 8;
            const uint32_t da = ua + (uint32_t)(row * (GSTR * 2) + f * 16);
            asm volatile("cp.async.cg.shared.global [%0], [%1], 16;" :: "r"(da), "l"(ga));
        }
#pragma unroll
        for (int i = 0; i < 4; ++i) {          // B: 128 rows x 64 halves
            const int s   = tid + i * 256;     // 0..1023
            const int row = s >> 3;
            const int f   = s & 7;
            const __half* gb = Bb + (size_t)row * K + kt * GBK + f * 8;
            const uint32_t db = ub + (uint32_t)(row * (GSTR * 2) + f * 16);
            asm volatile("cp.async.cg.shared.global [%0], [%1], 16;" :: "r"(db), "l"(gb));
        }
        asm volatile("cp.async.commit_group;" ::: "memory");
    };

    load_stage(0, 0);

    const int r = lane >> 2;
    const int c = lane & 3;

    for (int kt = 0; kt < nk; ++kt) {
        const int buf = kt & 1;
        asm volatile("cp.async.wait_group 0;" ::: "memory");
        __syncthreads();   // stage kt ready; all warps done reading buf^1
        if (kt + 1 < nk) load_stage(buf ^ 1, kt + 1);

        const __half* sa = smh + (size_t)buf * GSM_STG;
        const __half* sb = sa + GSM_A;

#pragma unroll
        for (int kk = 0; kk < 4; ++kk) {
            const int koff = kk * 16 + 4 * c;
            uint32_t afr[4][4];
            uint32_t bfr[8][2];
#pragma unroll
            for (int mt = 0; mt < 4; ++mt) {
                const __half* base = sa + (size_t)(wm + mt * 16 + r) * GSTR + koff;
                const uint2 u0 = *(const uint2*)base;
                const uint2 u8 = *(const uint2*)(base + 8 * GSTR);
                afr[mt][0] = u0.x; afr[mt][1] = u8.x;
                afr[mt][2] = u0.y; afr[mt][3] = u8.y;
            }
#pragma unroll
            for (int nt = 0; nt < 8; ++nt) {
                const uint2 bb = *(const uint2*)(
                    sb + (size_t)(wn + nt * 8 + r) * GSTR + koff);
                bfr[nt][0] = bb.x; bfr[nt][1] = bb.y;
            }
#pragma unroll
            for (int mt = 0; mt < 4; ++mt)
#pragma unroll
                for (int nt = 0; nt < 8; ++nt)
                    mma_f16(acc[mt][nt], afr[mt][0], afr[mt][1], afr[mt][2],
                            afr[mt][3], bfr[nt][0], bfr[nt][1]);
        }
    }

#pragma unroll
    for (int mt = 0; mt < 4; ++mt) {
        const int rg = m0 + wm + mt * 16 + r;
#pragma unroll
        for (int nt = 0; nt < 8; ++nt) {
            const int cgb = n0 + wn + nt * 8;
            const float b0 = bias[cgb + 2 * c], b1 = bias[cgb + 2 * c + 1];
            float v00 = acc[mt][nt][0] + b0, v01 = acc[mt][nt][1] + b1;
            float v10 = acc[mt][nt][2] + b0, v11 = acc[mt][nt][3] + b1;
            if (RELU) {
                v00 = fmaxf(v00, 0.f); v01 = fmaxf(v01, 0.f);
                v10 = fmaxf(v10, 0.f); v11 = fmaxf(v11, 0.f);
            }
            if (QSC && cgb < 1024) {
                v00 *= QSCALE_F; v01 *= QSCALE_F;
                v10 *= QSCALE_F; v11 *= QSCALE_F;
            }
            const int off = PERMOUT
                ? n0 + wn + (nt >> 1) * 16 + 4 * c + (nt & 1) * 2
                : cgb + 2 * c;
            *(uint32_t*)(C + (size_t)rg * N + off)       = h2pack(v00, v01);
            *(uint32_t*)(C + (size_t)(rg + 8) * N + off) = h2pack(v10, v11);
        }
    }
}

// ---------------------------------------------------------------------------
// fp16 flash attention (unchanged from R14): register-resident P, 3-stage KV.
// ---------------------------------------------------------------------------
#define FSTR 80
#define FA_TILE_H (64 * FSTR)
#define FA_SMEM_HALVES (6 * FA_TILE_H)
#define FA_SMEM_BYTES  (FA_SMEM_HALVES * 2)   // 61440

__global__ void __launch_bounds__(128, 2)
flash_attn(const __half* __restrict__ qkv, const __half* __restrict__ vt,
           __half* __restrict__ o)
{
    extern __shared__ __half fsh[];
    const int bh = blockIdx.y;
    const int b  = bh >> 4;
    const int h  = bh & 15;
    const int i0 = blockIdx.x * 128;

    const int tid  = threadIdx.x;
    const int lane = tid & 31;
    const int wid  = tid >> 5;
    const int r = lane >> 2;
    const int c = lane & 3;

    uint32_t qa[2][4][4];
    {
        const __half* qb = qkv + (size_t)(b * Sv + i0 + wid * 32) * QS + h * DKv;
#pragma unroll
        for (int mt = 0; mt < 2; ++mt)
#pragma unroll
            for (int g = 0; g < 4; ++g) {
                const __half* q0 = qb + (size_t)(mt * 16 + r) * QS + g * 16 + 4 * c;
                const __half* q8 = q0 + (size_t)8 * QS;
                const uint2 u0 = *(const uint2*)q0;
                const uint2 u8 = *(const uint2*)q8;
                qa[mt][g][0] = u0.x; qa[mt][g][1] = u8.x;
                qa[mt][g][2] = u0.y; qa[mt][g][3] = u8.y;
            }
    }

    float oacc[2][8][4] = {};
    float mrow[4] = { -1e30f, -1e30f, -1e30f, -1e30f };
    float lrow[4] = { 0.f, 0.f, 0.f, 0.f };

    auto load_kv = [&](int buf, int jt) {
        const __half* kb = qkv + (size_t)(b * Sv + jt * 64) * QS + 1024 + h * DKv;
        const __half* vb = vt + ((size_t)b * Dv + h * DKv) * Sv + jt * 64;
        const uint32_t uk = smem_u32(fsh + (size_t)buf * FA_TILE_H);
        const uint32_t uv = smem_u32(fsh + (size_t)(buf + 3) * FA_TILE_H);
#pragma unroll
        for (int i = 0; i < 4; ++i) {
            const int s   = tid + i * 128;
            const int row = s >> 3;
            const int f   = s & 7;
            const uint32_t dk_ = uk + (uint32_t)(row * (FSTR * 2) + f * 16);
            const uint32_t dv_ = uv + (uint32_t)(row * (FSTR * 2) + f * 16);
            asm volatile("cp.async.cg.shared.global [%0], [%1], 16;"
                         :: "r"(dk_), "l"(kb + (size_t)row * QS + f * 8));
            asm volatile("cp.async.cg.shared.global [%0], [%1], 16;"
                         :: "r"(dv_), "l"(vb + (size_t)row * Sv + f * 8));
        }
        asm volatile("cp.async.commit_group;" ::: "memory");
    };

    const int NT = Sv / 64;
    load_kv(0, 0);
    load_kv(1, 1);

    int buf = 0;
    for (int jt = 0; jt < NT; ++jt) {
        asm volatile("cp.async.wait_group 1;" ::: "memory");
        __syncthreads();
        if (jt + 2 < NT) {
            const int nb = (buf + 2 >= 3) ? buf - 1 : buf + 2;
            load_kv(nb, jt + 2);
        }

        const __half* ks = fsh + (size_t)buf * FA_TILE_H;
        const __half* vs = fsh + (size_t)(buf + 3) * FA_TILE_H;

        float sacc[2][8][4] = {};
#pragma unroll
        for (int g = 0; g < 4; ++g) {
            const int koff = g * 16 + 4 * c;
#pragma unroll
            for (int nt = 0; nt < 8; ++nt) {
                const uint2 bb = *(const uint2*)(
                    ks + (size_t)(nt * 8 + r) * FSTR + koff);
                mma_f16(sacc[0][nt], qa[0][g][0], qa[0][g][1], qa[0][g][2],
                        qa[0][g][3], bb.x, bb.y);
                mma_f16(sacc[1][nt], qa[1][g][0], qa[1][g][1], qa[1][g][2],
                        qa[1][g][3], bb.x, bb.y);
            }
        }

        uint32_t pa[2][4][4];
        float crl2[2], crh2[2];
#pragma unroll
        for (int mt = 0; mt < 2; ++mt) {
            float tl = -1e30f, th = -1e30f;
#pragma unroll
            for (int nt = 0; nt < 8; ++nt) {
                tl = fmaxf(tl, fmaxf(sacc[mt][nt][0], sacc[mt][nt][1]));
                th = fmaxf(th, fmaxf(sacc[mt][nt][2], sacc[mt][nt][3]));
            }
            tl = fmaxf(tl, __shfl_xor_sync(0xffffffffu, tl, 1));
            tl = fmaxf(tl, __shfl_xor_sync(0xffffffffu, tl, 2));
            th = fmaxf(th, __shfl_xor_sync(0xffffffffu, th, 1));
            th = fmaxf(th, __shfl_xor_sync(0xffffffffu, th, 2));

            const float mnl = fmaxf(mrow[2 * mt],     tl);
            const float mnh = fmaxf(mrow[2 * mt + 1], th);
            const float crl = exp2f(mrow[2 * mt]     - mnl);
            const float crh = exp2f(mrow[2 * mt + 1] - mnh);
            crl2[mt] = crl; crh2[mt] = crh;

            float sl = 0.f, sh = 0.f;
#pragma unroll
            for (int g = 0; g < 4; ++g) {
                const float p00 = exp2f(sacc[mt][2*g][0]   - mnl);
                const float p01 = exp2f(sacc[mt][2*g][1]   - mnl);
                const float p08 = exp2f(sacc[mt][2*g+1][0] - mnl);
                const float p09 = exp2f(sacc[mt][2*g+1][1] - mnl);
                const float p10 = exp2f(sacc[mt][2*g][2]   - mnh);
                const float p11 = exp2f(sacc[mt][2*g][3]   - mnh);
                const float p18 = exp2f(sacc[mt][2*g+1][2] - mnh);
                const float p19 = exp2f(sacc[mt][2*g+1][3] - mnh);
                sl += p00 + p01 + p08 + p09;
                sh += p10 + p11 + p18 + p19;
                pa[mt][g][0] = h2pack(p00, p01);
                pa[mt][g][1] = h2pack(p10, p11);
                pa[mt][g][2] = h2pack(p08, p09);
                pa[mt][g][3] = h2pack(p18, p19);
            }
            sl += __shfl_xor_sync(0xffffffffu, sl, 1);
            sl += __shfl_xor_sync(0xffffffffu, sl, 2);
            sh += __shfl_xor_sync(0xffffffffu, sh, 1);
            sh += __shfl_xor_sync(0xffffffffu, sh, 2);

            lrow[2 * mt]     = lrow[2 * mt]     * crl + sl;
            lrow[2 * mt + 1] = lrow[2 * mt + 1] * crh + sh;
            mrow[2 * mt]     = mnl;
            mrow[2 * mt + 1] = mnh;
        }

        const bool need = !__all_sync(0xffffffffu,
            (crl2[0] == 1.0f) && (crh2[0] == 1.0f) &&
            (crl2[1] == 1.0f) && (crh2[1] == 1.0f));
        if (need) {
#pragma unroll
            for (int mt = 0; mt < 2; ++mt)
#pragma unroll
                for (int nt = 0; nt < 8; ++nt) {
                    oacc[mt][nt][0] *= crl2[mt]; oacc[mt][nt][1] *= crl2[mt];
                    oacc[mt][nt][2] *= crh2[mt]; oacc[mt][nt][3] *= crh2[mt];
                }
        }

#pragma unroll
        for (int g = 0; g < 4; ++g) {
            const int koff = g * 16 + 4 * c;
#pragma unroll
            for (int nt = 0; nt < 8; ++nt) {
                const uint2 vv = *(const uint2*)(
                    vs + (size_t)(nt * 8 + r) * FSTR + koff);
                mma_f16(oacc[0][nt], pa[0][g][0], pa[0][g][1], pa[0][g][2],
                        pa[0][g][3], vv.x, vv.y);
                mma_f16(oacc[1][nt], pa[1][g][0], pa[1][g][1], pa[1][g][2],
                        pa[1][g][3], vv.x, vv.y);
            }
        }

        buf = (buf + 1 >= 3) ? 0 : buf + 1;
    }

#pragma unroll
    for (int mt = 0; mt < 2; ++mt) {
        const float inv_lo = 1.0f / lrow[2 * mt];
        const float inv_hi = 1.0f / lrow[2 * mt + 1];
        const size_t row_lo = (size_t)(b * Sv + i0 + wid * 32 + mt * 16 + r);
#pragma unroll
        for (int nt = 0; nt < 8; ++nt) {
            const int col = h * DKv + nt * 8 + 2 * c;
            *(uint32_t*)(o + row_lo * Dv + col) =
                h2pack(oacc[mt][nt][0] * inv_lo, oacc[mt][nt][1] * inv_lo);
            *(uint32_t*)(o + (row_lo + 8) * Dv + col) =
                h2pack(oacc[mt][nt][2] * inv_hi, oacc[mt][nt][3] * inv_hi);
        }
    }
}

// ---------------------------------------------------------------------------
// LN1: (x fp32 std + wo-out fp16 std) -> h fp16 perm16.
// ---------------------------------------------------------------------------
__global__ void __launch_bounds__(256) residual_ln1(
    const float* __restrict__ a, const __half* __restrict__ r,
    const float* __restrict__ g, const float* __restrict__ be,
    __half* __restrict__ outh)
{
    const size_t row = (size_t)blockIdx.x * 8 + (threadIdx.x >> 5);
    const int lane = threadIdx.x & 31;

    float v[32];
    float s = 0.f, s2 = 0.f;
#pragma unroll
    for (int gg = 0; gg < 4; ++gg) {
        const int gb = (gg * 32 + lane) * 8;
        const float4 a0 = *(const float4*)(a + row * Dv + gb);
        const float4 a1 = *(const float4*)(a + row * Dv + gb + 4);
        const uint4 ru = *(const uint4*)(r + row * Dv + gb);
        const float2 r0 = __half22float2(*(const __half2*)&ru.x);
        const float2 r1 = __half22float2(*(const __half2*)&ru.y);
        const float2 r2 = __half22float2(*(const __half2*)&ru.z);
        const float2 r3 = __half22float2(*(const __half2*)&ru.w);
        float* vv = v + gg * 8;
        vv[0] = a0.x + r0.x; vv[1] = a0.y + r0.y;
        vv[2] = a0.z + r1.x; vv[3] = a0.w + r1.y;
        vv[4] = a1.x + r2.x; vv[5] = a1.y + r2.y;
        vv[6] = a1.z + r3.x; vv[7] = a1.w + r3.y;
#pragma unroll
        for (int i = 0; i < 8; ++i) { s += vv[i]; s2 += vv[i] * vv[i]; }
    }
#pragma unroll
    for (int o_ = 16; o_ > 0; o_ >>= 1) {
        s  += __shfl_xor_sync(0xffffffffu, s,  o_);
        s2 += __shfl_xor_sync(0xffffffffu, s2, o_);
    }
    const float mu  = s * (1.0f / Dv);
    const float var = s2 * (1.0f / Dv) - mu * mu;
    const float inv = rsqrtf(var + LN_EPS);

#pragma unroll
    for (int gg = 0; gg < 4; ++gg) {
        const int G  = gg * 32 + lane;
        const int gb = G * 8;
        const float4 g0 = *(const float4*)(g + gb);
        const float4 g1v = *(const float4*)(g + gb + 4);
        const float4 b0 = *(const float4*)(be + gb);
        const float4 b1v = *(const float4*)(be + gb + 4);
        const float* vv = v + gg * 8;
        float y[8];
        y[0] = (vv[0] - mu) * inv * g0.x  + b0.x;
        y[1] = (vv[1] - mu) * inv * g0.y  + b0.y;
        y[2] = (vv[2] - mu) * inv * g0.z  + b0.z;
        y[3] = (vv[3] - mu) * inv * g0.w  + b0.w;
        y[4] = (vv[4] - mu) * inv * g1v.x + b1v.x;
        y[5] = (vv[5] - mu) * inv * g1v.y + b1v.y;
        y[6] = (vv[6] - mu) * inv * g1v.z + b1v.z;
        y[7] = (vv[7] - mu) * inv * g1v.w + b1v.w;
        __half* hb = outh + row * Dv + (G >> 1) * 16 + (G & 1) * 2;
        *(uint32_t*)(hb + 0)  = h2pack(y[0], y[1]);
        *(uint32_t*)(hb + 4)  = h2pack(y[2], y[3]);
        *(uint32_t*)(hb + 8)  = h2pack(y[4], y[5]);
        *(uint32_t*)(hb + 12) = h2pack(y[6], y[7]);
    }
}

// ---------------------------------------------------------------------------
// LN2: (h fp16 PERM16 + ff2-out fp16 std) -> out fp32 standard.
// ---------------------------------------------------------------------------
__global__ void __launch_bounds__(256) residual_ln2(
    const __half* __restrict__ a, const __half* __restrict__ r,
    const float* __restrict__ g, const float* __restrict__ be,
    float* __restrict__ out)
{
    const size_t row = (size_t)blockIdx.x * 8 + (threadIdx.x >> 5);
    const int lane = threadIdx.x & 31;

    float v[32];
    float s = 0.f, s2 = 0.f;
#pragma unroll
    for (int gg = 0; gg < 2; ++gg) {
        const int G16 = gg * 32 + lane;
        const int gb = G16 * 16;
        const uint4 au0 = *(const uint4*)(a + row * Dv + gb);
        const uint4 au1 = *(const uint4*)(a + row * Dv + gb + 8);
        const uint4 ru0 = *(const uint4*)(r + row * Dv + gb);
        const uint4 ru1 = *(const uint4*)(r + row * Dv + gb + 8);
        float as[16], rs[16];
        {
            const float2 p0 = __half22float2(*(const __half2*)&au0.x);
            const float2 p1 = __half22float2(*(const __half2*)&au0.y);
            const float2 p2 = __half22float2(*(const __half2*)&au0.z);
            const float2 p3 = __half22float2(*(const __half2*)&au0.w);
            const float2 p4 = __half22float2(*(const __half2*)&au1.x);
            const float2 p5 = __half22float2(*(const __half2*)&au1.y);
            const float2 p6 = __half22float2(*(const __half2*)&au1.z);
            const float2 p7 = __half22float2(*(const __half2*)&au1.w);
            as[0]  = p0.x; as[1]  = p0.y;
            as[8]  = p1.x; as[9]  = p1.y;
            as[2]  = p2.x; as[3]  = p2.y;
            as[10] = p3.x; as[11] = p3.y;
            as[4]  = p4.x; as[5]  = p4.y;
            as[12] = p5.x; as[13] = p5.y;
            as[6]  = p6.x; as[7]  = p6.y;
            as[14] = p7.x; as[15] = p7.y;
        }
        {
            const float2 p0 = __half22float2(*(const __half2*)&ru0.x);
            const float2 p1 = __half22float2(*(const __half2*)&ru0.y);
            const float2 p2 = __half22float2(*(const __half2*)&ru0.z);
            const float2 p3 = __half22float2(*(const __half2*)&ru0.w);
            const float2 p4 = __half22float2(*(const __half2*)&ru1.x);
            const float2 p5 = __half22float2(*(const __half2*)&ru1.y);
            const float2 p6 = __half22float2(*(const __half2*)&ru1.z);
            const float2 p7 = __half22float2(*(const __half2*)&ru1.w);
            rs[0]  = p0.x; rs[1]  = p0.y; rs[2]  = p1.x; rs[3]  = p1.y;
            rs[4]  = p2.x; rs[5]  = p2.y; rs[6]  = p3.x; rs[7]  = p3.y;
            rs[8]  = p4.x; rs[9]  = p4.y; rs[10] = p5.x; rs[11] = p5.y;
            rs[12] = p6.x; rs[13] = p6.y; rs[14] = p7.x; rs[15] = p7.y;
        }
        float* vv = v + gg * 16;
#pragma unroll
        for (int i = 0; i < 16; ++i) {
            vv[i] = as[i] + rs[i];
            s += vv[i]; s2 += vv[i] * vv[i];
        }
    }
#pragma unroll
    for (int o_ = 16; o_ > 0; o_ >>= 1) {
        s  += __shfl_xor_sync(0xffffffffu, s,  o_);
        s2 += __shfl_xor_sync(0xffffffffu, s2, o_);
    }
    const float mu  = s * (1.0f / Dv);
    const float var = s2 * (1.0f / Dv) - mu * mu;
    const float inv = rsqrtf(var + LN_EPS);

#pragma unroll
    for (int gg = 0; gg < 2; ++gg) {
        const int gb = (gg * 32 + lane) * 16;
        const float* vv = v + gg * 16;
#pragma unroll
        for (int q = 0; q < 4; ++q) {
            const float4 gv = *(const float4*)(g + gb + q * 4);
            const float4 bv = *(const float4*)(be + gb + q * 4);
            float4 ov;
            ov.x = (vv[q*4+0] - mu) * inv * gv.x + bv.x;
            ov.y = (vv[q*4+1] - mu) * inv * gv.y + bv.y;
            ov.z = (vv[q*4+2] - mu) * inv * gv.z + bv.z;
            ov.w = (vv[q*4+3] - mu) * inv * gv.w + bv.w;
            *(float4*)(out + row * Dv + gb + q * 4) = ov;
        }
    }
}

// ---------------------------------------------------------------------------
// Launch
// ---------------------------------------------------------------------------
extern "C" void kernel_launch(void* const* d_in, const int* in_sizes, int n_in,
                              void* d_out, int out_size)
{
    const float* x  = (const float*)d_in[0];
    const float* wq = (const float*)d_in[1];
    const float* bq = (const float*)d_in[2];
    const float* wk = (const float*)d_in[3];
    const float* bk = (const float*)d_in[4];
    const float* wv = (const float*)d_in[5];
    const float* bv = (const float*)d_in[6];
    const float* wo = (const float*)d_in[7];
    const float* bo = (const float*)d_in[8];
    const float* w1 = (const float*)d_in[9];
    const float* b1 = (const float*)d_in[10];
    const float* w2 = (const float*)d_in[11];
    const float* b2 = (const float*)d_in[12];
    const float* g1 = (const float*)d_in[13];
    const float* be1= (const float*)d_in[14];
    const float* g2 = (const float*)d_in[15];
    const float* be2= (const float*)d_in[16];
    float* out = (float*)d_out;

    __half *qkv, *xr, *attn, *hh, *ff1, *vt, *wh, *tmp, *tmp2;
    float *bqkv;
    cudaGetSymbolAddress((void**)&qkv,  g_qkv);
    cudaGetSymbolAddress((void**)&xr,   g_xr);
    cudaGetSymbolAddress((void**)&attn, g_attn);
    cudaGetSymbolAddress((void**)&hh,   g_h);
    cudaGetSymbolAddress((void**)&ff1,  g_ff1);
    cudaGetSymbolAddress((void**)&vt,   g_vt);
    cudaGetSymbolAddress((void**)&wh,   g_w);
    cudaGetSymbolAddress((void**)&tmp,  g_tmp);
    cudaGetSymbolAddress((void**)&tmp2, g_tmp2);
    cudaGetSymbolAddress((void**)&bqkv, g_bqkv);

    const size_t MB1 = 1024 * 1024;
    __half* wqkvT = wh;               // [3072][1024]
    __half* woT   = wh + 3 * MB1;
    __half* w1T   = wh + 4 * MB1;     // [F, D]
    __half* w2T   = wh + 8 * MB1;     // [D, F]

    cudaFuncSetAttribute(gemm_h<false, true,  true >,
        cudaFuncAttributeMaxDynamicSharedMemorySize, GSMEM_BYTES);
    cudaFuncSetAttribute(gemm_h<false, false, false>,
        cudaFuncAttributeMaxDynamicSharedMemorySize, GSMEM_BYTES);
    cudaFuncSetAttribute(gemm_h<true,  true,  false>,
        cudaFuncAttributeMaxDynamicSharedMemorySize, GSMEM_BYTES);
    cudaFuncSetAttribute(flash_attn,
        cudaFuncAttributeMaxDynamicSharedMemorySize, FA_SMEM_BYTES);

    // All weight/input prep in ONE launch
    mega_prep<<<MEGA_BLOCKS, 256>>>(wq, wk, wv, wo, w1, w2, x,
                                    bq, bk, bv, wh, xr, bqkv);

    // QKV projection -> qkv fp16 (cols perm16, q pre-scaled)
    gemm_h<false, true, true><<<dim3(QS / 128, Mv / 256), 256, GSMEM_BYTES>>>(
        Dv, QS, xr, wqkvT, bqkv, qkv);

    // V transpose for fp16 PV fragments
    dim3 tb(32, 8);
    transpose_v<<<dim3(Sv / 64, Dv / 64, Bv), tb>>>(qkv, vt);

    // Flash attention -> attn fp16 (dperm); register P, 3-stage KV pipeline
    flash_attn<<<dim3(Sv / 128, Bv * Hv), 128, FA_SMEM_BYTES>>>(qkv, vt, attn);

    const dim3 gDD(Dv / 128, Mv / 256);   // (8, 16)
    const dim3 gDF(Fv / 128, Mv / 256);   // (32, 16)

    // Output projection (fp16 standard) + LN1 (fp16 perm h)
    gemm_h<false, false, false><<<gDD, 256, GSMEM_BYTES>>>(Dv, Dv, attn, woT, bo, tmp);
    residual_ln1<<<Mv / 8, 256>>>(x, tmp, g1, be1, hh);

    // FFN + LN2 (residual read from fp16 perm h)
    gemm_h<true,  true,  false><<<gDF, 256, GSMEM_BYTES>>>(Dv, Fv, hh, w1T, b1, ff1);
    gemm_h<false, false, false><<<gDD, 256, GSMEM_BYTES>>>(Fv, Dv, ff1, w2T, b2, tmp2);
    residual_ln2<<<Mv / 8, 256>>>(hh, tmp2, g2, be2, out);
}

// round 16
// speedup vs baseline: 1.0181x; 1.0181x over previous
#include <cuda_runtime.h>
#include <cuda_fp16.h>
#include <cstdint>

// Problem constants
#define Bv   2
#define Sv   2048
#define Dv   1024
#define Hv   16
#define DKv  64
#define Fv   4096
#define Mv   (Bv * Sv)      // 4096 rows
#define QS   3072           // qkv row stride (halves)
#define LN_EPS 1e-6f
#define QSCALE_F (0.125f * 1.4426950408889634f)

// fp16 k-permutation: within each 16-group, pair p=(k&15)>>1 stored at slot
// perm8(p) = p<4 ? 2p : 2p-7. Slot order of a 16-group:
//   [l0,l1, l8,l9, l2,l3, l10,l11, l4,l5, l12,l13, l6,l7, l14,l15]

// ---------------------------------------------------------------------------
// Scratch
// ---------------------------------------------------------------------------
__device__ __half g_qkv [(size_t)Mv * QS];            // q|k|v fp16, d perm16 (q pre-scaled)
__device__ __half g_xr  [(size_t)Mv * Dv];            // x fp16, perm16
__device__ __half g_attn[(size_t)Mv * Dv];            // flash out fp16, perm16
__device__ __half g_h   [(size_t)Mv * Dv];            // LN1 out fp16, perm16
__device__ __half g_ff1 [(size_t)Mv * Fv];            // ff1 out fp16, perm16
__device__ __half g_vt  [(size_t)Bv * Dv * Sv];       // V transposed [b][d][jperm]
__device__ __half g_tmp [(size_t)Mv * Dv];            // wo out fp16 STANDARD
__device__ __half g_tmp2[(size_t)Mv * Dv];            // ff2 out fp16 STANDARD
__device__ __half g_w   [(size_t)12 * 1024 * 1024];   // fp16 weights, k perm16
__device__ float  g_bqkv[QS];

// ---------------------------------------------------------------------------
// Helpers
// ---------------------------------------------------------------------------
__device__ __forceinline__ uint32_t smem_u32(const void* p) {
    uint32_t a;
    asm("{ .reg .u64 t; cvta.to.shared.u64 t, %1; cvt.u32.u64 %0, t; }"
        : "=r"(a) : "l"(p));
    return a;
}
__device__ __forceinline__ int perm8i(int t) { return (t < 4) ? 2 * t : 2 * t - 7; }
__device__ __forceinline__ int kperm16(int k) {
    return (k & ~15) | (2 * perm8i((k & 15) >> 1) + (k & 1));
}
__device__ __forceinline__ uint32_t h2pack(float x, float y) {
    __half2 h = __floats2half2_rn(x, y);
    return *(uint32_t*)&h;
}
__device__ __forceinline__ void mma_f16(
    float* d, uint32_t a0, uint32_t a1, uint32_t a2, uint32_t a3,
    uint32_t b0, uint32_t b1)
{
    asm volatile(
        "mma.sync.aligned.m16n8k16.row.col.f32.f16.f16.f32 "
        "{%0,%1,%2,%3}, {%4,%5,%6,%7}, {%8,%9}, {%0,%1,%2,%3};"
        : "+f"(d[0]), "+f"(d[1]), "+f"(d[2]), "+f"(d[3])
        : "r"(a0), "r"(a1), "r"(a2), "r"(a3), "r"(b0), "r"(b1));
}

// ---------------------------------------------------------------------------
// Mega prep: ONE launch, all weight transposes + x rounding + bias pack.
// ---------------------------------------------------------------------------
#define MEGA_BLOCKS 13315

__device__ __forceinline__ void transpose_tile_f16(
    const float* __restrict__ W, __half* __restrict__ WT,
    int K, int N, int k0, int n0, int tx, int ty0)
{
    __shared__ float t[32][33];
#pragma unroll
    for (int i = 0; i < 4; ++i) {
        const int ty = ty0 + i * 8;
        t[ty][tx] = W[(size_t)(k0 + ty) * N + n0 + tx];
    }
    __syncthreads();
    const int txs = kperm16(tx);
#pragma unroll
    for (int i = 0; i < 4; ++i) {
        const int ty = ty0 + i * 8;
        WT[(size_t)(n0 + ty) * K + k0 + txs] = __float2half_rn(t[tx][ty]);
    }
}

__global__ void __launch_bounds__(256) mega_prep(
    const float* __restrict__ wq, const float* __restrict__ wk,
    const float* __restrict__ wv, const float* __restrict__ wo,
    const float* __restrict__ w1, const float* __restrict__ w2,
    const float* __restrict__ x,
    const float* __restrict__ bq, const float* __restrict__ bk,
    const float* __restrict__ bv,
    __half* __restrict__ wdst, __half* __restrict__ xr,
    float* __restrict__ bias)
{
    const int idx = blockIdx.x;
    const int tid = threadIdx.x;

    if (idx < 12288) {
        const int tx  = tid & 31;
        const int ty0 = tid >> 5;
        const float* W; __half* WT; int K, N, kt, nt;
        if (idx < 4096) {
            const int m = idx >> 10, tile = idx & 1023;
            const float* srcs[4] = { wq, wk, wv, wo };
            W = srcs[m]; WT = wdst + (size_t)m * Dv * Dv;
            K = Dv; N = Dv; kt = tile >> 5; nt = tile & 31;
        } else if (idx < 8192) {
            const int tile = idx - 4096;
            W = w1; WT = wdst + (size_t)4 * 1024 * 1024;
            K = Dv; N = Fv; kt = tile & 31; nt = tile >> 5;
        } else {
            const int tile = idx - 8192;
            W = w2; WT = wdst + (size_t)8 * 1024 * 1024;
            K = Fv; N = Dv; kt = tile >> 5; nt = tile & 31;
        }
        transpose_tile_f16(W, WT, K, N, kt * 32, nt * 32, tx, ty0);
    } else if (idx < 13312) {
        const int blk = idx - 12288;
        const size_t base = ((size_t)blk * 256 + tid) * 16;
        const float4 a = *(const float4*)(x + base);
        const float4 b = *(const float4*)(x + base + 4);
        const float4 cc = *(const float4*)(x + base + 8);
        const float4 d = *(const float4*)(x + base + 12);
        uint4 u0, u1;
        u0.x = h2pack(a.x, a.y);   u0.y = h2pack(cc.x, cc.y);
        u0.z = h2pack(a.z, a.w);   u0.w = h2pack(cc.z, cc.w);
        u1.x = h2pack(b.x, b.y);   u1.y = h2pack(d.x, d.y);
        u1.z = h2pack(b.z, b.w);   u1.w = h2pack(d.z, d.w);
        *(uint4*)(xr + base)     = u0;
        *(uint4*)(xr + base + 8) = u1;
    } else {
        const int j = idx - 13312;   // 0..2
        const float* src = (j == 0) ? bq : (j == 1) ? bk : bv;
        ((float4*)bias)[j * 256 + tid] = ((const float4*)src)[tid];
    }
}

// ---------------------------------------------------------------------------
// V transpose: qkv V-part [token][dperm] -> vt[b][dperm][jperm]
// ---------------------------------------------------------------------------
__global__ void __launch_bounds__(256) transpose_v(
    const __half* __restrict__ qkv, __half* __restrict__ vt)
{
    __shared__ __half t[64][66];
    const int j0 = blockIdx.x * 64, d0 = blockIdx.y * 64, b = blockIdx.z;
    const int tx = threadIdx.x, ty = threadIdx.y;   // 32 x 8

#pragma unroll
    for (int i = 0; i < 8; ++i) {
        const int j = ty + i * 8;
        const __half2 v = *(const __half2*)(
            qkv + (size_t)(b * Sv + j0 + j) * QS + 2048 + d0 + 2 * tx);
        t[2 * tx][j]     = __low2half(v);
        t[2 * tx + 1][j] = __high2half(v);
    }
    __syncthreads();
    const int js0 = kperm16(tx);
    const int js1 = kperm16(tx + 32);
#pragma unroll
    for (int i = 0; i < 8; ++i) {
        const int d = ty + i * 8;
        __half* dst = vt + ((size_t)b * Dv + d0 + d) * Sv + j0;
        dst[js0] = t[d][tx];
        dst[js1] = t[d][tx + 32];
    }
}

// ---------------------------------------------------------------------------
// fp16 tensor-core GEMM (proven best config): 128 threads, 4 warps 2x2 of
// 64x64 (128x128 CTA tile), BK=64, 2-stage cp.async, single barrier/k-tile.
// ---------------------------------------------------------------------------
#define GBK 64
#define GSTR 80
#define GSM_H (128 * GSTR)
#define GSMEM_BYTES (4 * GSM_H * 2)   // 81920

template <bool RELU, bool PERMOUT, bool QSC>
__global__ void __launch_bounds__(128)
gemm_h(int K, int N, const __half* __restrict__ A,
       const __half* __restrict__ W, const float* __restrict__ bias,
       __half* __restrict__ C)
{
    extern __shared__ __half smh[];
    const int m0 = blockIdx.y * 128;
    const int n0 = blockIdx.x * 128;
    const int tid  = threadIdx.x;
    const int lane = tid & 31;
    const int wid  = tid >> 5;
    const int wm = (wid >> 1) * 64;
    const int wn = (wid & 1) * 64;

    __half* tA[2] = { smh,           smh + 2 * GSM_H };
    __half* tB[2] = { smh + GSM_H,   smh + 3 * GSM_H };
    const uint32_t uA[2] = { smem_u32(tA[0]), smem_u32(tA[1]) };
    const uint32_t uB[2] = { smem_u32(tB[0]), smem_u32(tB[1]) };

    const __half* Ab = A + (size_t)m0 * K;
    const __half* Bb = W + (size_t)n0 * K;
    const int nk = K / GBK;

    float acc[4][8][4] = {};

    auto load_stage = [&](int buf, int kt) {
#pragma unroll
        for (int i = 0; i < 8; ++i) {
            const int s   = tid + i * 128;   // 0..1023
            const int row = s >> 3;
            const int f   = s & 7;
            const __half* ga = Ab + (size_t)row * K + kt * GBK + f * 8;
            const __half* gb = Bb + (size_t)row * K + kt * GBK + f * 8;
            const uint32_t da = uA[buf] + (uint32_t)(row * (GSTR * 2) + f * 16);
            const uint32_t db = uB[buf] + (uint32_t)(row * (GSTR * 2) + f * 16);
            asm volatile("cp.async.cg.shared.global [%0], [%1], 16;" :: "r"(da), "l"(ga));
            asm volatile("cp.async.cg.shared.global [%0], [%1], 16;" :: "r"(db), "l"(gb));
        }
        asm volatile("cp.async.commit_group;" ::: "memory");
    };

    load_stage(0, 0);

    const int r = lane >> 2;
    const int c = lane & 3;

    for (int kt = 0; kt < nk; ++kt) {
        const int buf = kt & 1;
        asm volatile("cp.async.wait_group 0;" ::: "memory");
        __syncthreads();   // stage ready; all warps done reading buf^1
        if (kt + 1 < nk) load_stage(buf ^ 1, kt + 1);

        const __half* sa = tA[buf];
        const __half* sb = tB[buf];

#pragma unroll
        for (int kk = 0; kk < 4; ++kk) {
            const int koff = kk * 16 + 4 * c;
            uint32_t afr[4][4];
            uint32_t bfr[8][2];
#pragma unroll
            for (int mt = 0; mt < 4; ++mt) {
                const __half* base = sa + (size_t)(wm + mt * 16 + r) * GSTR + koff;
                const uint2 u0 = *(const uint2*)base;
                const uint2 u8 = *(const uint2*)(base + 8 * GSTR);
                afr[mt][0] = u0.x; afr[mt][1] = u8.x;
                afr[mt][2] = u0.y; afr[mt][3] = u8.y;
            }
#pragma unroll
            for (int nt = 0; nt < 8; ++nt) {
                const uint2 bb = *(const uint2*)(
                    sb + (size_t)(wn + nt * 8 + r) * GSTR + koff);
                bfr[nt][0] = bb.x; bfr[nt][1] = bb.y;
            }
#pragma unroll
            for (int mt = 0; mt < 4; ++mt)
#pragma unroll
                for (int nt = 0; nt < 8; ++nt)
                    mma_f16(acc[mt][nt], afr[mt][0], afr[mt][1], afr[mt][2],
                            afr[mt][3], bfr[nt][0], bfr[nt][1]);
        }
    }

#pragma unroll
    for (int mt = 0; mt < 4; ++mt) {
        const int rg = m0 + wm + mt * 16 + r;
#pragma unroll
        for (int nt = 0; nt < 8; ++nt) {
            const int cgb = n0 + wn + nt * 8;
            const float b0 = bias[cgb + 2 * c], b1 = bias[cgb + 2 * c + 1];
            float v00 = acc[mt][nt][0] + b0, v01 = acc[mt][nt][1] + b1;
            float v10 = acc[mt][nt][2] + b0, v11 = acc[mt][nt][3] + b1;
            if (RELU) {
                v00 = fmaxf(v00, 0.f); v01 = fmaxf(v01, 0.f);
                v10 = fmaxf(v10, 0.f); v11 = fmaxf(v11, 0.f);
            }
            if (QSC && cgb < 1024) {
                v00 *= QSCALE_F; v01 *= QSCALE_F;
                v10 *= QSCALE_F; v11 *= QSCALE_F;
            }
            const int off = PERMOUT
                ? n0 + wn + (nt >> 1) * 16 + 4 * c + (nt & 1) * 2
                : cgb + 2 * c;
            *(uint32_t*)(C + (size_t)rg * N + off)       = h2pack(v00, v01);
            *(uint32_t*)(C + (size_t)(rg + 8) * N + off) = h2pack(v10, v11);
        }
    }
}

// ---------------------------------------------------------------------------
// fp16 flash attention: register-resident P, 3-stage KV pipeline, and
// PAIRED fp16 exp2 (ex2.approx.f16x2) -> halved MUFU pressure. The h2exp2
// result IS the PV A-fragment (P was fp16-rounded anyway).
// ---------------------------------------------------------------------------
#define FSTR 80
#define FA_TILE_H (64 * FSTR)
#define FA_SMEM_HALVES (6 * FA_TILE_H)
#define FA_SMEM_BYTES  (FA_SMEM_HALVES * 2)   // 61440

__global__ void __launch_bounds__(128, 2)
flash_attn(const __half* __restrict__ qkv, const __half* __restrict__ vt,
           __half* __restrict__ o)
{
    extern __shared__ __half fsh[];
    const int bh = blockIdx.y;
    const int b  = bh >> 4;
    const int h  = bh & 15;
    const int i0 = blockIdx.x * 128;

    const int tid  = threadIdx.x;
    const int lane = tid & 31;
    const int wid  = tid >> 5;
    const int r = lane >> 2;
    const int c = lane & 3;

    uint32_t qa[2][4][4];
    {
        const __half* qb = qkv + (size_t)(b * Sv + i0 + wid * 32) * QS + h * DKv;
#pragma unroll
        for (int mt = 0; mt < 2; ++mt)
#pragma unroll
            for (int g = 0; g < 4; ++g) {
                const __half* q0 = qb + (size_t)(mt * 16 + r) * QS + g * 16 + 4 * c;
                const __half* q8 = q0 + (size_t)8 * QS;
                const uint2 u0 = *(const uint2*)q0;
                const uint2 u8 = *(const uint2*)q8;
                qa[mt][g][0] = u0.x; qa[mt][g][1] = u8.x;
                qa[mt][g][2] = u0.y; qa[mt][g][3] = u8.y;
            }
    }

    float oacc[2][8][4] = {};
    float mrow[4] = { -1e30f, -1e30f, -1e30f, -1e30f };
    float lrow[4] = { 0.f, 0.f, 0.f, 0.f };

    auto load_kv = [&](int buf, int jt) {
        const __half* kb = qkv + (size_t)(b * Sv + jt * 64) * QS + 1024 + h * DKv;
        const __half* vb = vt + ((size_t)b * Dv + h * DKv) * Sv + jt * 64;
        const uint32_t uk = smem_u32(fsh + (size_t)buf * FA_TILE_H);
        const uint32_t uv = smem_u32(fsh + (size_t)(buf + 3) * FA_TILE_H);
#pragma unroll
        for (int i = 0; i < 4; ++i) {
            const int s   = tid + i * 128;
            const int row = s >> 3;
            const int f   = s & 7;
            const uint32_t dk_ = uk + (uint32_t)(row * (FSTR * 2) + f * 16);
            const uint32_t dv_ = uv + (uint32_t)(row * (FSTR * 2) + f * 16);
            asm volatile("cp.async.cg.shared.global [%0], [%1], 16;"
                         :: "r"(dk_), "l"(kb + (size_t)row * QS + f * 8));
            asm volatile("cp.async.cg.shared.global [%0], [%1], 16;"
                         :: "r"(dv_), "l"(vb + (size_t)row * Sv + f * 8));
        }
        asm volatile("cp.async.commit_group;" ::: "memory");
    };

    const int NT = Sv / 64;
    load_kv(0, 0);
    load_kv(1, 1);

    int buf = 0;
    for (int jt = 0; jt < NT; ++jt) {
        asm volatile("cp.async.wait_group 1;" ::: "memory");
        __syncthreads();
        if (jt + 2 < NT) {
            const int nb = (buf + 2 >= 3) ? buf - 1 : buf + 2;
            load_kv(nb, jt + 2);
        }

        const __half* ks = fsh + (size_t)buf * FA_TILE_H;
        const __half* vs = fsh + (size_t)(buf + 3) * FA_TILE_H;

        // ---- S = Q K^T (log2 domain) ----
        float sacc[2][8][4] = {};
#pragma unroll
        for (int g = 0; g < 4; ++g) {
            const int koff = g * 16 + 4 * c;
#pragma unroll
            for (int nt = 0; nt < 8; ++nt) {
                const uint2 bb = *(const uint2*)(
                    ks + (size_t)(nt * 8 + r) * FSTR + koff);
                mma_f16(sacc[0][nt], qa[0][g][0], qa[0][g][1], qa[0][g][2],
                        qa[0][g][3], bb.x, bb.y);
                mma_f16(sacc[1][nt], qa[1][g][0], qa[1][g][1], qa[1][g][2],
                        qa[1][g][3], bb.x, bb.y);
            }
        }

        // ---- base-2 online softmax; paired fp16 exp2 -> PV A-fragments ----
        uint32_t pa[2][4][4];
        float crl2[2], crh2[2];
#pragma unroll
        for (int mt = 0; mt < 2; ++mt) {
            float tl = -1e30f, th = -1e30f;
#pragma unroll
            for (int nt = 0; nt < 8; ++nt) {
                tl = fmaxf(tl, fmaxf(sacc[mt][nt][0], sacc[mt][nt][1]));
                th = fmaxf(th, fmaxf(sacc[mt][nt][2], sacc[mt][nt][3]));
            }
            tl = fmaxf(tl, __shfl_xor_sync(0xffffffffu, tl, 1));
            tl = fmaxf(tl, __shfl_xor_sync(0xffffffffu, tl, 2));
            th = fmaxf(th, __shfl_xor_sync(0xffffffffu, th, 1));
            th = fmaxf(th, __shfl_xor_sync(0xffffffffu, th, 2));

            const float mnl = fmaxf(mrow[2 * mt],     tl);
            const float mnh = fmaxf(mrow[2 * mt + 1], th);
            const float crl = exp2f(mrow[2 * mt]     - mnl);
            const float crh = exp2f(mrow[2 * mt + 1] - mnh);
            crl2[mt] = crl; crh2[mt] = crh;

            float sl = 0.f, sh = 0.f;
#pragma unroll
            for (int g = 0; g < 4; ++g) {
                // two fp16 exps per MUFU op; result already in A-frag layout
                const __half2 e00 = h2exp2(__floats2half2_rn(
                    sacc[mt][2*g][0]   - mnl, sacc[mt][2*g][1]   - mnl));
                const __half2 e08 = h2exp2(__floats2half2_rn(
                    sacc[mt][2*g+1][0] - mnl, sacc[mt][2*g+1][1] - mnl));
                const __half2 e10 = h2exp2(__floats2half2_rn(
                    sacc[mt][2*g][2]   - mnh, sacc[mt][2*g][3]   - mnh));
                const __half2 e18 = h2exp2(__floats2half2_rn(
                    sacc[mt][2*g+1][2] - mnh, sacc[mt][2*g+1][3] - mnh));
                pa[mt][g][0] = *(const uint32_t*)&e00;
                pa[mt][g][1] = *(const uint32_t*)&e10;
                pa[mt][g][2] = *(const uint32_t*)&e08;
                pa[mt][g][3] = *(const uint32_t*)&e18;
                const float2 f00 = __half22float2(e00);
                const float2 f08 = __half22float2(e08);
                const float2 f10 = __half22float2(e10);
                const float2 f18 = __half22float2(e18);
                sl += (f00.x + f00.y) + (f08.x + f08.y);
                sh += (f10.x + f10.y) + (f18.x + f18.y);
            }
            sl += __shfl_xor_sync(0xffffffffu, sl, 1);
            sl += __shfl_xor_sync(0xffffffffu, sl, 2);
            sh += __shfl_xor_sync(0xffffffffu, sh, 1);
            sh += __shfl_xor_sync(0xffffffffu, sh, 2);

            lrow[2 * mt]     = lrow[2 * mt]     * crl + sl;
            lrow[2 * mt + 1] = lrow[2 * mt + 1] * crh + sh;
            mrow[2 * mt]     = mnl;
            mrow[2 * mt + 1] = mnh;
        }

        // Rescale O only when some row's max moved (warp-coherent vote).
        const bool need = !__all_sync(0xffffffffu,
            (crl2[0] == 1.0f) && (crh2[0] == 1.0f) &&
            (crl2[1] == 1.0f) && (crh2[1] == 1.0f));
        if (need) {
#pragma unroll
            for (int mt = 0; mt < 2; ++mt)
#pragma unroll
                for (int nt = 0; nt < 8; ++nt) {
                    oacc[mt][nt][0] *= crl2[mt]; oacc[mt][nt][1] *= crl2[mt];
                    oacc[mt][nt][2] *= crh2[mt]; oacc[mt][nt][3] *= crh2[mt];
                }
        }

        // ---- O += P V (P in registers; V B-frags from jperm vt) ----
#pragma unroll
        for (int g = 0; g < 4; ++g) {
            const int koff = g * 16 + 4 * c;
#pragma unroll
            for (int nt = 0; nt < 8; ++nt) {
                const uint2 vv = *(const uint2*)(
                    vs + (size_t)(nt * 8 + r) * FSTR + koff);
                mma_f16(oacc[0][nt], pa[0][g][0], pa[0][g][1], pa[0][g][2],
                        pa[0][g][3], vv.x, vv.y);
                mma_f16(oacc[1][nt], pa[1][g][0], pa[1][g][1], pa[1][g][2],
                        pa[1][g][3], vv.x, vv.y);
            }
        }

        buf = (buf + 1 >= 3) ? 0 : buf + 1;
    }

    // ---- epilogue: normalize, fp16 store (cols already dperm) ----
#pragma unroll
    for (int mt = 0; mt < 2; ++mt) {
        const float inv_lo = 1.0f / lrow[2 * mt];
        const float inv_hi = 1.0f / lrow[2 * mt + 1];
        const size_t row_lo = (size_t)(b * Sv + i0 + wid * 32 + mt * 16 + r);
#pragma unroll
        for (int nt = 0; nt < 8; ++nt) {
            const int col = h * DKv + nt * 8 + 2 * c;
            *(uint32_t*)(o + row_lo * Dv + col) =
                h2pack(oacc[mt][nt][0] * inv_lo, oacc[mt][nt][1] * inv_lo);
            *(uint32_t*)(o + (row_lo + 8) * Dv + col) =
                h2pack(oacc[mt][nt][2] * inv_hi, oacc[mt][nt][3] * inv_hi);
        }
    }
}

// ---------------------------------------------------------------------------
// LN1: (x fp32 std + wo-out fp16 std) -> h fp16 perm16.
// ---------------------------------------------------------------------------
__global__ void __launch_bounds__(256) residual_ln1(
    const float* __restrict__ a, const __half* __restrict__ r,
    const float* __restrict__ g, const float* __restrict__ be,
    __half* __restrict__ outh)
{
    const size_t row = (size_t)blockIdx.x * 8 + (threadIdx.x >> 5);
    const int lane = threadIdx.x & 31;

    float v[32];
    float s = 0.f, s2 = 0.f;
#pragma unroll
    for (int gg = 0; gg < 4; ++gg) {
        const int gb = (gg * 32 + lane) * 8;
        const float4 a0 = *(const float4*)(a + row * Dv + gb);
        const float4 a1 = *(const float4*)(a + row * Dv + gb + 4);
        const uint4 ru = *(const uint4*)(r + row * Dv + gb);
        const float2 r0 = __half22float2(*(const __half2*)&ru.x);
        const float2 r1 = __half22float2(*(const __half2*)&ru.y);
        const float2 r2 = __half22float2(*(const __half2*)&ru.z);
        const float2 r3 = __half22float2(*(const __half2*)&ru.w);
        float* vv = v + gg * 8;
        vv[0] = a0.x + r0.x; vv[1] = a0.y + r0.y;
        vv[2] = a0.z + r1.x; vv[3] = a0.w + r1.y;
        vv[4] = a1.x + r2.x; vv[5] = a1.y + r2.y;
        vv[6] = a1.z + r3.x; vv[7] = a1.w + r3.y;
#pragma unroll
        for (int i = 0; i < 8; ++i) { s += vv[i]; s2 += vv[i] * vv[i]; }
    }
#pragma unroll
    for (int o_ = 16; o_ > 0; o_ >>= 1) {
        s  += __shfl_xor_sync(0xffffffffu, s,  o_);
        s2 += __shfl_xor_sync(0xffffffffu, s2, o_);
    }
    const float mu  = s * (1.0f / Dv);
    const float var = s2 * (1.0f / Dv) - mu * mu;
    const float inv = rsqrtf(var + LN_EPS);

#pragma unroll
    for (int gg = 0; gg < 4; ++gg) {
        const int G  = gg * 32 + lane;
        const int gb = G * 8;
        const float4 g0 = *(const float4*)(g + gb);
        const float4 g1v = *(const float4*)(g + gb + 4);
        const float4 b0 = *(const float4*)(be + gb);
        const float4 b1v = *(const float4*)(be + gb + 4);
        const float* vv = v + gg * 8;
        float y[8];
        y[0] = (vv[0] - mu) * inv * g0.x  + b0.x;
        y[1] = (vv[1] - mu) * inv * g0.y  + b0.y;
        y[2] = (vv[2] - mu) * inv * g0.z  + b0.z;
        y[3] = (vv[3] - mu) * inv * g0.w  + b0.w;
        y[4] = (vv[4] - mu) * inv * g1v.x + b1v.x;
        y[5] = (vv[5] - mu) * inv * g1v.y + b1v.y;
        y[6] = (vv[6] - mu) * inv * g1v.z + b1v.z;
        y[7] = (vv[7] - mu) * inv * g1v.w + b1v.w;
        __half* hb = outh + row * Dv + (G >> 1) * 16 + (G & 1) * 2;
        *(uint32_t*)(hb + 0)  = h2pack(y[0], y[1]);
        *(uint32_t*)(hb + 4)  = h2pack(y[2], y[3]);
        *(uint32_t*)(hb + 8)  = h2pack(y[4], y[5]);
        *(uint32_t*)(hb + 12) = h2pack(y[6], y[7]);
    }
}

// ---------------------------------------------------------------------------
// LN2: (h fp16 PERM16 + ff2-out fp16 std) -> out fp32 standard.
// ---------------------------------------------------------------------------
__global__ void __launch_bounds__(256) residual_ln2(
    const __half* __restrict__ a, const __half* __restrict__ r,
    const float* __restrict__ g, const float* __restrict__ be,
    float* __restrict__ out)
{
    const size_t row = (size_t)blockIdx.x * 8 + (threadIdx.x >> 5);
    const int lane = threadIdx.x & 31;

    float v[32];
    float s = 0.f, s2 = 0.f;
#pragma unroll
    for (int gg = 0; gg < 2; ++gg) {
        const int G16 = gg * 32 + lane;
        const int gb = G16 * 16;
        const uint4 au0 = *(const uint4*)(a + row * Dv + gb);
        const uint4 au1 = *(const uint4*)(a + row * Dv + gb + 8);
        const uint4 ru0 = *(const uint4*)(r + row * Dv + gb);
        const uint4 ru1 = *(const uint4*)(r + row * Dv + gb + 8);
        float as[16], rs[16];
        {
            const float2 p0 = __half22float2(*(const __half2*)&au0.x);
            const float2 p1 = __half22float2(*(const __half2*)&au0.y);
            const float2 p2 = __half22float2(*(const __half2*)&au0.z);
            const float2 p3 = __half22float2(*(const __half2*)&au0.w);
            const float2 p4 = __half22float2(*(const __half2*)&au1.x);
            const float2 p5 = __half22float2(*(const __half2*)&au1.y);
            const float2 p6 = __half22float2(*(const __half2*)&au1.z);
            const float2 p7 = __half22float2(*(const __half2*)&au1.w);
            as[0]  = p0.x; as[1]  = p0.y;
            as[8]  = p1.x; as[9]  = p1.y;
            as[2]  = p2.x; as[3]  = p2.y;
            as[10] = p3.x; as[11] = p3.y;
            as[4]  = p4.x; as[5]  = p4.y;
            as[12] = p5.x; as[13] = p5.y;
            as[6]  = p6.x; as[7]  = p6.y;
            as[14] = p7.x; as[15] = p7.y;
        }
        {
            const float2 p0 = __half22float2(*(const __half2*)&ru0.x);
            const float2 p1 = __half22float2(*(const __half2*)&ru0.y);
            const float2 p2 = __half22float2(*(const __half2*)&ru0.z);
            const float2 p3 = __half22float2(*(const __half2*)&ru0.w);
            const float2 p4 = __half22float2(*(const __half2*)&ru1.x);
            const float2 p5 = __half22float2(*(const __half2*)&ru1.y);
            const float2 p6 = __half22float2(*(const __half2*)&ru1.z);
            const float2 p7 = __half22float2(*(const __half2*)&ru1.w);
            rs[0]  = p0.x; rs[1]  = p0.y; rs[2]  = p1.x; rs[3]  = p1.y;
            rs[4]  = p2.x; rs[5]  = p2.y; rs[6]  = p3.x; rs[7]  = p3.y;
            rs[8]  = p4.x; rs[9]  = p4.y; rs[10] = p5.x; rs[11] = p5.y;
            rs[12] = p6.x; rs[13] = p6.y; rs[14] = p7.x; rs[15] = p7.y;
        }
        float* vv = v + gg * 16;
#pragma unroll
        for (int i = 0; i < 16; ++i) {
            vv[i] = as[i] + rs[i];
            s += vv[i]; s2 += vv[i] * vv[i];
        }
    }
#pragma unroll
    for (int o_ = 16; o_ > 0; o_ >>= 1) {
        s  += __shfl_xor_sync(0xffffffffu, s,  o_);
        s2 += __shfl_xor_sync(0xffffffffu, s2, o_);
    }
    const float mu  = s * (1.0f / Dv);
    const float var = s2 * (1.0f / Dv) - mu * mu;
    const float inv = rsqrtf(var + LN_EPS);

#pragma unroll
    for (int gg = 0; gg < 2; ++gg) {
        const int gb = (gg * 32 + lane) * 16;
        const float* vv = v + gg * 16;
#pragma unroll
        for (int q = 0; q < 4; ++q) {
            const float4 gv = *(const float4*)(g + gb + q * 4);
            const float4 bv = *(const float4*)(be + gb + q * 4);
            float4 ov;
            ov.x = (vv[q*4+0] - mu) * inv * gv.x + bv.x;
            ov.y = (vv[q*4+1] - mu) * inv * gv.y + bv.y;
            ov.z = (vv[q*4+2] - mu) * inv * gv.z + bv.z;
            ov.w = (vv[q*4+3] - mu) * inv * gv.w + bv.w;
            *(float4*)(out + row * Dv + gb + q * 4) = ov;
        }
    }
}

// ---------------------------------------------------------------------------
// Launch
// ---------------------------------------------------------------------------
extern "C" void kernel_launch(void* const* d_in, const int* in_sizes, int n_in,
                              void* d_out, int out_size)
{
    const float* x  = (const float*)d_in[0];
    const float* wq = (const float*)d_in[1];
    const float* bq = (const float*)d_in[2];
    const float* wk = (const float*)d_in[3];
    const float* bk = (const float*)d_in[4];
    const float* wv = (const float*)d_in[5];
    const float* bv = (const float*)d_in[6];
    const float* wo = (const float*)d_in[7];
    const float* bo = (const float*)d_in[8];
    const float* w1 = (const float*)d_in[9];
    const float* b1 = (const float*)d_in[10];
    const float* w2 = (const float*)d_in[11];
    const float* b2 = (const float*)d_in[12];
    const float* g1 = (const float*)d_in[13];
    const float* be1= (const float*)d_in[14];
    const float* g2 = (const float*)d_in[15];
    const float* be2= (const float*)d_in[16];
    float* out = (float*)d_out;

    __half *qkv, *xr, *attn, *hh, *ff1, *vt, *wh, *tmp, *tmp2;
    float *bqkv;
    cudaGetSymbolAddress((void**)&qkv,  g_qkv);
    cudaGetSymbolAddress((void**)&xr,   g_xr);
    cudaGetSymbolAddress((void**)&attn, g_attn);
    cudaGetSymbolAddress((void**)&hh,   g_h);
    cudaGetSymbolAddress((void**)&ff1,  g_ff1);
    cudaGetSymbolAddress((void**)&vt,   g_vt);
    cudaGetSymbolAddress((void**)&wh,   g_w);
    cudaGetSymbolAddress((void**)&tmp,  g_tmp);
    cudaGetSymbolAddress((void**)&tmp2, g_tmp2);
    cudaGetSymbolAddress((void**)&bqkv, g_bqkv);

    const size_t MB1 = 1024 * 1024;
    __half* wqkvT = wh;               // [3072][1024]
    __half* woT   = wh + 3 * MB1;
    __half* w1T   = wh + 4 * MB1;     // [F, D]
    __half* w2T   = wh + 8 * MB1;     // [D, F]

    cudaFuncSetAttribute(gemm_h<false, true,  true >,
        cudaFuncAttributeMaxDynamicSharedMemorySize, GSMEM_BYTES);
    cudaFuncSetAttribute(gemm_h<false, false, false>,
        cudaFuncAttributeMaxDynamicSharedMemorySize, GSMEM_BYTES);
    cudaFuncSetAttribute(gemm_h<true,  true,  false>,
        cudaFuncAttributeMaxDynamicSharedMemorySize, GSMEM_BYTES);
    cudaFuncSetAttribute(flash_attn,
        cudaFuncAttributeMaxDynamicSharedMemorySize, FA_SMEM_BYTES);

    // All weight/input prep in ONE launch
    mega_prep<<<MEGA_BLOCKS, 256>>>(wq, wk, wv, wo, w1, w2, x,
                                    bq, bk, bv, wh, xr, bqkv);

    // QKV projection -> qkv fp16 (cols perm16, q pre-scaled)
    gemm_h<false, true, true><<<dim3(QS / 128, Mv / 128), 128, GSMEM_BYTES>>>(
        Dv, QS, xr, wqkvT, bqkv, qkv);

    // V transpose for fp16 PV fragments
    dim3 tb(32, 8);
    transpose_v<<<dim3(Sv / 64, Dv / 64, Bv), tb>>>(qkv, vt);

    // Flash attention -> attn fp16 (dperm); register P, paired fp16 exp2
    flash_attn<<<dim3(Sv / 128, Bv * Hv), 128, FA_SMEM_BYTES>>>(qkv, vt, attn);

    const dim3 gDD(Dv / 128, Mv / 128);   // (8, 32)
    const dim3 gDF(Fv / 128, Mv / 128);   // (32, 32)

    // Output projection (fp16 standard) + LN1 (fp16 perm h)
    gemm_h<false, false, false><<<gDD, 128, GSMEM_BYTES>>>(Dv, Dv, attn, woT, bo, tmp);
    residual_ln1<<<Mv / 8, 256>>>(x, tmp, g1, be1, hh);

    // FFN + LN2 (residual read from fp16 perm h)
    gemm_h<true,  true,  false><<<gDF, 128, GSMEM_BYTES>>>(Dv, Fv, hh, w1T, b1, ff1);
    gemm_h<false, false, false><<<gDD, 128, GSMEM_BYTES>>>(Fv, Dv, ff1, w2T, b2, tmp2);
    residual_ln2<<<Mv / 8, 256>>>(hh, tmp2, g2, be2, out);
}

// round 17
// speedup vs baseline: 1.0632x; 1.0443x over previous
#include <cuda_runtime.h>
#include <cuda_fp16.h>
#include <cstdint>

// Problem constants
#define Bv   2
#define Sv   2048
#define Dv   1024
#define Hv   16
#define DKv  64
#define Fv   4096
#define Mv   (Bv * Sv)      // 4096 rows
#define QS   3072           // qkv row stride (halves)
#define LN_EPS 1e-6f
#define QSCALE_F (0.125f * 1.4426950408889634f)

// fp16 k-permutation: within each 16-group, pair p=(k&15)>>1 stored at slot
// perm8(p) = p<4 ? 2p : 2p-7. Slot order of a 16-group:
//   [l0,l1, l8,l9, l2,l3, l10,l11, l4,l5, l12,l13, l6,l7, l14,l15]

// ---------------------------------------------------------------------------
// Scratch
// ---------------------------------------------------------------------------
__device__ __half g_qkv [(size_t)Mv * QS];            // q|k|v fp16, d perm16 (q pre-scaled)
__device__ __half g_xr  [(size_t)Mv * Dv];            // x fp16, perm16
__device__ __half g_attn[(size_t)Mv * Dv];            // flash out fp16, perm16
__device__ __half g_h   [(size_t)Mv * Dv];            // LN1 out fp16, perm16
__device__ float  g_hf  [(size_t)Mv * Dv];            // LN1 out fp32, standard
__device__ __half g_ff1 [(size_t)Mv * Fv];            // ff1 out fp16, perm16
__device__ __half g_vt  [(size_t)Bv * Dv * Sv];       // V transposed [b][d][jperm]
__device__ __half g_tmp [(size_t)Mv * Dv];            // wo out fp16 STANDARD
__device__ __half g_tmp2[(size_t)Mv * Dv];            // ff2 out fp16 STANDARD
__device__ __half g_w   [(size_t)12 * 1024 * 1024];   // fp16 weights, k perm16
__device__ float  g_bqkv[QS];

// ---------------------------------------------------------------------------
// Helpers
// ---------------------------------------------------------------------------
__device__ __forceinline__ uint32_t smem_u32(const void* p) {
    uint32_t a;
    asm("{ .reg .u64 t; cvta.to.shared.u64 t, %1; cvt.u32.u64 %0, t; }"
        : "=r"(a) : "l"(p));
    return a;
}
__device__ __forceinline__ int perm8i(int t) { return (t < 4) ? 2 * t : 2 * t - 7; }
__device__ __forceinline__ int kperm16(int k) {
    return (k & ~15) | (2 * perm8i((k & 15) >> 1) + (k & 1));
}
__device__ __forceinline__ uint32_t h2pack(float x, float y) {
    __half2 h = __floats2half2_rn(x, y);
    return *(uint32_t*)&h;
}
__device__ __forceinline__ void mma_f16(
    float* d, uint32_t a0, uint32_t a1, uint32_t a2, uint32_t a3,
    uint32_t b0, uint32_t b1)
{
    asm volatile(
        "mma.sync.aligned.m16n8k16.row.col.f32.f16.f16.f32 "
        "{%0,%1,%2,%3}, {%4,%5,%6,%7}, {%8,%9}, {%0,%1,%2,%3};"
        : "+f"(d[0]), "+f"(d[1]), "+f"(d[2]), "+f"(d[3])
        : "r"(a0), "r"(a1), "r"(a2), "r"(a3), "r"(b0), "r"(b1));
}

// ---------------------------------------------------------------------------
// Mega prep: ONE launch, all weight transposes + x rounding + bias pack.
// ---------------------------------------------------------------------------
#define MEGA_BLOCKS 13315

__device__ __forceinline__ void transpose_tile_f16(
    const float* __restrict__ W, __half* __restrict__ WT,
    int K, int N, int k0, int n0, int tx, int ty0)
{
    __shared__ float t[32][33];
#pragma unroll
    for (int i = 0; i < 4; ++i) {
        const int ty = ty0 + i * 8;
        t[ty][tx] = W[(size_t)(k0 + ty) * N + n0 + tx];
    }
    __syncthreads();
    const int txs = kperm16(tx);
#pragma unroll
    for (int i = 0; i < 4; ++i) {
        const int ty = ty0 + i * 8;
        WT[(size_t)(n0 + ty) * K + k0 + txs] = __float2half_rn(t[tx][ty]);
    }
}

__global__ void __launch_bounds__(256) mega_prep(
    const float* __restrict__ wq, const float* __restrict__ wk,
    const float* __restrict__ wv, const float* __restrict__ wo,
    const float* __restrict__ w1, const float* __restrict__ w2,
    const float* __restrict__ x,
    const float* __restrict__ bq, const float* __restrict__ bk,
    const float* __restrict__ bv,
    __half* __restrict__ wdst, __half* __restrict__ xr,
    float* __restrict__ bias)
{
    const int idx = blockIdx.x;
    const int tid = threadIdx.x;

    if (idx < 12288) {
        const int tx  = tid & 31;
        const int ty0 = tid >> 5;
        const float* W; __half* WT; int K, N, kt, nt;
        if (idx < 4096) {
            const int m = idx >> 10, tile = idx & 1023;
            const float* srcs[4] = { wq, wk, wv, wo };
            W = srcs[m]; WT = wdst + (size_t)m * Dv * Dv;
            K = Dv; N = Dv; kt = tile >> 5; nt = tile & 31;
        } else if (idx < 8192) {
            const int tile = idx - 4096;
            W = w1; WT = wdst + (size_t)4 * 1024 * 1024;
            K = Dv; N = Fv; kt = tile & 31; nt = tile >> 5;
        } else {
            const int tile = idx - 8192;
            W = w2; WT = wdst + (size_t)8 * 1024 * 1024;
            K = Fv; N = Dv; kt = tile >> 5; nt = tile & 31;
        }
        transpose_tile_f16(W, WT, K, N, kt * 32, nt * 32, tx, ty0);
    } else if (idx < 13312) {
        const int blk = idx - 12288;
        const size_t base = ((size_t)blk * 256 + tid) * 16;
        const float4 a = *(const float4*)(x + base);
        const float4 b = *(const float4*)(x + base + 4);
        const float4 cc = *(const float4*)(x + base + 8);
        const float4 d = *(const float4*)(x + base + 12);
        uint4 u0, u1;
        u0.x = h2pack(a.x, a.y);   u0.y = h2pack(cc.x, cc.y);
        u0.z = h2pack(a.z, a.w);   u0.w = h2pack(cc.z, cc.w);
        u1.x = h2pack(b.x, b.y);   u1.y = h2pack(d.x, d.y);
        u1.z = h2pack(b.z, b.w);   u1.w = h2pack(d.z, d.w);
        *(uint4*)(xr + base)     = u0;
        *(uint4*)(xr + base + 8) = u1;
    } else {
        const int j = idx - 13312;   // 0..2
        const float* src = (j == 0) ? bq : (j == 1) ? bk : bv;
        ((float4*)bias)[j * 256 + tid] = ((const float4*)src)[tid];
    }
}

// ---------------------------------------------------------------------------
// V transpose: qkv V-part [token][dperm] -> vt[b][dperm][jperm]
// ---------------------------------------------------------------------------
__global__ void __launch_bounds__(256) transpose_v(
    const __half* __restrict__ qkv, __half* __restrict__ vt)
{
    __shared__ __half t[64][66];
    const int j0 = blockIdx.x * 64, d0 = blockIdx.y * 64, b = blockIdx.z;
    const int tx = threadIdx.x, ty = threadIdx.y;   // 32 x 8

#pragma unroll
    for (int i = 0; i < 8; ++i) {
        const int j = ty + i * 8;
        const __half2 v = *(const __half2*)(
            qkv + (size_t)(b * Sv + j0 + j) * QS + 2048 + d0 + 2 * tx);
        t[2 * tx][j]     = __low2half(v);
        t[2 * tx + 1][j] = __high2half(v);
    }
    __syncthreads();
    const int js0 = kperm16(tx);
    const int js1 = kperm16(tx + 32);
#pragma unroll
    for (int i = 0; i < 8; ++i) {
        const int d = ty + i * 8;
        __half* dst = vt + ((size_t)b * Dv + d0 + d) * Sv + j0;
        dst[js0] = t[d][tx];
        dst[js1] = t[d][tx + 32];
    }
}

// ---------------------------------------------------------------------------
// fp16 tensor-core GEMM: 128 threads, 4 warps 2x2 of 64x64 (128x128 CTA
// tile), BK=64, 2-stage cp.async, single barrier/k-tile, and REGISTER
// DOUBLE-BUFFERED fragments: kk+1's LDS issued before kk's MMAs so the
// 29-cy LDS latency is hidden behind tensor work.
// ---------------------------------------------------------------------------
#define GBK 64
#define GSTR 80
#define GSM_H (128 * GSTR)
#define GSMEM_BYTES (4 * GSM_H * 2)   // 81920

template <bool RELU, bool PERMOUT, bool QSC>
__global__ void __launch_bounds__(128)
gemm_h(int K, int N, const __half* __restrict__ A,
       const __half* __restrict__ W, const float* __restrict__ bias,
       __half* __restrict__ C)
{
    extern __shared__ __half smh[];
    const int m0 = blockIdx.y * 128;
    const int n0 = blockIdx.x * 128;
    const int tid  = threadIdx.x;
    const int lane = tid & 31;
    const int wid  = tid >> 5;
    const int wm = (wid >> 1) * 64;
    const int wn = (wid & 1) * 64;

    __half* tA[2] = { smh,           smh + 2 * GSM_H };
    __half* tB[2] = { smh + GSM_H,   smh + 3 * GSM_H };
    const uint32_t uA[2] = { smem_u32(tA[0]), smem_u32(tA[1]) };
    const uint32_t uB[2] = { smem_u32(tB[0]), smem_u32(tB[1]) };

    const __half* Ab = A + (size_t)m0 * K;
    const __half* Bb = W + (size_t)n0 * K;
    const int nk = K / GBK;

    float acc[4][8][4] = {};

    auto load_stage = [&](int buf, int kt) {
#pragma unroll
        for (int i = 0; i < 8; ++i) {
            const int s   = tid + i * 128;   // 0..1023
            const int row = s >> 3;
            const int f   = s & 7;
            const __half* ga = Ab + (size_t)row * K + kt * GBK + f * 8;
            const __half* gb = Bb + (size_t)row * K + kt * GBK + f * 8;
            const uint32_t da = uA[buf] + (uint32_t)(row * (GSTR * 2) + f * 16);
            const uint32_t db = uB[buf] + (uint32_t)(row * (GSTR * 2) + f * 16);
            asm volatile("cp.async.cg.shared.global [%0], [%1], 16;" :: "r"(da), "l"(ga));
            asm volatile("cp.async.cg.shared.global [%0], [%1], 16;" :: "r"(db), "l"(gb));
        }
        asm volatile("cp.async.commit_group;" ::: "memory");
    };

    load_stage(0, 0);

    const int r = lane >> 2;
    const int c = lane & 3;

    uint32_t afr[2][4][4];   // double-buffered A fragments
    uint32_t bfr[2][8][2];   // double-buffered B fragments

    auto load_frags = [&](const __half* sa, const __half* sb, int kk, int pb) {
        const int koff = kk * 16 + 4 * c;
#pragma unroll
        for (int mt = 0; mt < 4; ++mt) {
            const __half* base = sa + (size_t)(wm + mt * 16 + r) * GSTR + koff;
            const uint2 u0 = *(const uint2*)base;
            const uint2 u8 = *(const uint2*)(base + 8 * GSTR);
            afr[pb][mt][0] = u0.x; afr[pb][mt][1] = u8.x;
            afr[pb][mt][2] = u0.y; afr[pb][mt][3] = u8.y;
        }
#pragma unroll
        for (int nt = 0; nt < 8; ++nt) {
            const uint2 bb = *(const uint2*)(
                sb + (size_t)(wn + nt * 8 + r) * GSTR + koff);
            bfr[pb][nt][0] = bb.x; bfr[pb][nt][1] = bb.y;
        }
    };

    for (int kt = 0; kt < nk; ++kt) {
        const int buf = kt & 1;
        asm volatile("cp.async.wait_group 0;" ::: "memory");
        __syncthreads();   // stage ready; all warps done reading buf^1
        if (kt + 1 < nk) load_stage(buf ^ 1, kt + 1);

        const __half* sa = tA[buf];
        const __half* sb = tB[buf];

        load_frags(sa, sb, 0, 0);
#pragma unroll
        for (int kk = 0; kk < 4; ++kk) {
            const int cur = kk & 1;
            if (kk < 3) load_frags(sa, sb, kk + 1, cur ^ 1);
#pragma unroll
            for (int mt = 0; mt < 4; ++mt)
#pragma unroll
                for (int nt = 0; nt < 8; ++nt)
                    mma_f16(acc[mt][nt],
                            afr[cur][mt][0], afr[cur][mt][1],
                            afr[cur][mt][2], afr[cur][mt][3],
                            bfr[cur][nt][0], bfr[cur][nt][1]);
        }
    }

#pragma unroll
    for (int mt = 0; mt < 4; ++mt) {
        const int rg = m0 + wm + mt * 16 + r;
#pragma unroll
        for (int nt = 0; nt < 8; ++nt) {
            const int cgb = n0 + wn + nt * 8;
            const float b0 = bias[cgb + 2 * c], b1 = bias[cgb + 2 * c + 1];
            float v00 = acc[mt][nt][0] + b0, v01 = acc[mt][nt][1] + b1;
            float v10 = acc[mt][nt][2] + b0, v11 = acc[mt][nt][3] + b1;
            if (RELU) {
                v00 = fmaxf(v00, 0.f); v01 = fmaxf(v01, 0.f);
                v10 = fmaxf(v10, 0.f); v11 = fmaxf(v11, 0.f);
            }
            if (QSC && cgb < 1024) {
                v00 *= QSCALE_F; v01 *= QSCALE_F;
                v10 *= QSCALE_F; v11 *= QSCALE_F;
            }
            const int off = PERMOUT
                ? n0 + wn + (nt >> 1) * 16 + 4 * c + (nt & 1) * 2
                : cgb + 2 * c;
            *(uint32_t*)(C + (size_t)rg * N + off)       = h2pack(v00, v01);
            *(uint32_t*)(C + (size_t)(rg + 8) * N + off) = h2pack(v10, v11);
        }
    }
}

// ---------------------------------------------------------------------------
// fp16 flash attention (R13 version — best measured): register-resident P,
// 2-stage KV double buffer, scalar fp32 exp2f softmax.
// ---------------------------------------------------------------------------
#define FSTR 80
#define FA_SMEM_HALVES (4 * 64 * FSTR)   // K+V double buffers
#define FA_SMEM_BYTES  (FA_SMEM_HALVES * 2)   // 40960

__global__ void __launch_bounds__(128, 2)
flash_attn(const __half* __restrict__ qkv, const __half* __restrict__ vt,
           __half* __restrict__ o)
{
    extern __shared__ __half fsh[];
    __half* Kt[2] = { fsh,               fsh + 64 * FSTR };
    __half* Vt[2] = { fsh + 2*64*FSTR,   fsh + 3*64*FSTR };

    const int bh = blockIdx.y;
    const int b  = bh >> 4;
    const int h  = bh & 15;
    const int i0 = blockIdx.x * 128;

    const int tid  = threadIdx.x;
    const int lane = tid & 31;
    const int wid  = tid >> 5;
    const int r = lane >> 2;
    const int c = lane & 3;

    const uint32_t uK[2] = { smem_u32(Kt[0]), smem_u32(Kt[1]) };
    const uint32_t uV[2] = { smem_u32(Vt[0]), smem_u32(Vt[1]) };

    uint32_t qa[2][4][4];
    {
        const __half* qb = qkv + (size_t)(b * Sv + i0 + wid * 32) * QS + h * DKv;
#pragma unroll
        for (int mt = 0; mt < 2; ++mt)
#pragma unroll
            for (int g = 0; g < 4; ++g) {
                const __half* q0 = qb + (size_t)(mt * 16 + r) * QS + g * 16 + 4 * c;
                const __half* q8 = q0 + (size_t)8 * QS;
                const uint2 u0 = *(const uint2*)q0;
                const uint2 u8 = *(const uint2*)q8;
                qa[mt][g][0] = u0.x; qa[mt][g][1] = u8.x;
                qa[mt][g][2] = u0.y; qa[mt][g][3] = u8.y;
            }
    }

    float oacc[2][8][4] = {};
    float mrow[4] = { -1e30f, -1e30f, -1e30f, -1e30f };
    float lrow[4] = { 0.f, 0.f, 0.f, 0.f };

    auto load_kv = [&](int buf, int jt) {
        const __half* kb = qkv + (size_t)(b * Sv + jt * 64) * QS + 1024 + h * DKv;
        const __half* vb = vt + ((size_t)b * Dv + h * DKv) * Sv + jt * 64;
#pragma unroll
        for (int i = 0; i < 4; ++i) {
            const int s   = tid + i * 128;
            const int row = s >> 3;
            const int f   = s & 7;
            const uint32_t dk_ = uK[buf] + (uint32_t)(row * (FSTR * 2) + f * 16);
            const uint32_t dv_ = uV[buf] + (uint32_t)(row * (FSTR * 2) + f * 16);
            asm volatile("cp.async.cg.shared.global [%0], [%1], 16;"
                         :: "r"(dk_), "l"(kb + (size_t)row * QS + f * 8));
            asm volatile("cp.async.cg.shared.global [%0], [%1], 16;"
                         :: "r"(dv_), "l"(vb + (size_t)row * Sv + f * 8));
        }
        asm volatile("cp.async.commit_group;" ::: "memory");
    };

    load_kv(0, 0);

    const int NT = Sv / 64;
    for (int jt = 0; jt < NT; ++jt) {
        const int buf = jt & 1;
        asm volatile("cp.async.wait_group 0;" ::: "memory");
        __syncthreads();
        if (jt + 1 < NT) load_kv(buf ^ 1, jt + 1);

        const __half* ks = Kt[buf];
        const __half* vs = Vt[buf];

        // ---- S = Q K^T (log2 domain) ----
        float sacc[2][8][4] = {};
#pragma unroll
        for (int g = 0; g < 4; ++g) {
            const int koff = g * 16 + 4 * c;
#pragma unroll
            for (int nt = 0; nt < 8; ++nt) {
                const uint2 bb = *(const uint2*)(
                    ks + (size_t)(nt * 8 + r) * FSTR + koff);
                mma_f16(sacc[0][nt], qa[0][g][0], qa[0][g][1], qa[0][g][2],
                        qa[0][g][3], bb.x, bb.y);
                mma_f16(sacc[1][nt], qa[1][g][0], qa[1][g][1], qa[1][g][2],
                        qa[1][g][3], bb.x, bb.y);
            }
        }

        // ---- base-2 online softmax; P packed straight into A-fragments ----
        uint32_t pa[2][4][4];
        float crl2[2], crh2[2];
#pragma unroll
        for (int mt = 0; mt < 2; ++mt) {
            float tl = -1e30f, th = -1e30f;
#pragma unroll
            for (int nt = 0; nt < 8; ++nt) {
                tl = fmaxf(tl, fmaxf(sacc[mt][nt][0], sacc[mt][nt][1]));
                th = fmaxf(th, fmaxf(sacc[mt][nt][2], sacc[mt][nt][3]));
            }
            tl = fmaxf(tl, __shfl_xor_sync(0xffffffffu, tl, 1));
            tl = fmaxf(tl, __shfl_xor_sync(0xffffffffu, tl, 2));
            th = fmaxf(th, __shfl_xor_sync(0xffffffffu, th, 1));
            th = fmaxf(th, __shfl_xor_sync(0xffffffffu, th, 2));

            const float mnl = fmaxf(mrow[2 * mt],     tl);
            const float mnh = fmaxf(mrow[2 * mt + 1], th);
            const float crl = exp2f(mrow[2 * mt]     - mnl);
            const float crh = exp2f(mrow[2 * mt + 1] - mnh);
            crl2[mt] = crl; crh2[mt] = crh;

            float sl = 0.f, sh = 0.f;
#pragma unroll
            for (int g = 0; g < 4; ++g) {
                const float p00 = exp2f(sacc[mt][2*g][0]   - mnl);
                const float p01 = exp2f(sacc[mt][2*g][1]   - mnl);
                const float p08 = exp2f(sacc[mt][2*g+1][0] - mnl);
                const float p09 = exp2f(sacc[mt][2*g+1][1] - mnl);
                const float p10 = exp2f(sacc[mt][2*g][2]   - mnh);
                const float p11 = exp2f(sacc[mt][2*g][3]   - mnh);
                const float p18 = exp2f(sacc[mt][2*g+1][2] - mnh);
                const float p19 = exp2f(sacc[mt][2*g+1][3] - mnh);
                sl += p00 + p01 + p08 + p09;
                sh += p10 + p11 + p18 + p19;
                pa[mt][g][0] = h2pack(p00, p01);
                pa[mt][g][1] = h2pack(p10, p11);
                pa[mt][g][2] = h2pack(p08, p09);
                pa[mt][g][3] = h2pack(p18, p19);
            }
            sl += __shfl_xor_sync(0xffffffffu, sl, 1);
            sl += __shfl_xor_sync(0xffffffffu, sl, 2);
            sh += __shfl_xor_sync(0xffffffffu, sh, 1);
            sh += __shfl_xor_sync(0xffffffffu, sh, 2);

            lrow[2 * mt]     = lrow[2 * mt]     * crl + sl;
            lrow[2 * mt + 1] = lrow[2 * mt + 1] * crh + sh;
            mrow[2 * mt]     = mnl;
            mrow[2 * mt + 1] = mnh;
        }

        // Rescale O only when some row's max moved (warp-coherent vote).
        const bool need = !__all_sync(0xffffffffu,
            (crl2[0] == 1.0f) && (crh2[0] == 1.0f) &&
            (crl2[1] == 1.0f) && (crh2[1] == 1.0f));
        if (need) {
#pragma unroll
            for (int mt = 0; mt < 2; ++mt)
#pragma unroll
                for (int nt = 0; nt < 8; ++nt) {
                    oacc[mt][nt][0] *= crl2[mt]; oacc[mt][nt][1] *= crl2[mt];
                    oacc[mt][nt][2] *= crh2[mt]; oacc[mt][nt][3] *= crh2[mt];
                }
        }

        // ---- O += P V (P in registers; V B-frags from jperm vt) ----
#pragma unroll
        for (int g = 0; g < 4; ++g) {
            const int koff = g * 16 + 4 * c;
#pragma unroll
            for (int nt = 0; nt < 8; ++nt) {
                const uint2 vv = *(const uint2*)(
                    vs + (size_t)(nt * 8 + r) * FSTR + koff);
                mma_f16(oacc[0][nt], pa[0][g][0], pa[0][g][1], pa[0][g][2],
                        pa[0][g][3], vv.x, vv.y);
                mma_f16(oacc[1][nt], pa[1][g][0], pa[1][g][1], pa[1][g][2],
                        pa[1][g][3], vv.x, vv.y);
            }
        }
    }

    // ---- epilogue: normalize, fp16 store (cols already dperm) ----
#pragma unroll
    for (int mt = 0; mt < 2; ++mt) {
        const float inv_lo = 1.0f / lrow[2 * mt];
        const float inv_hi = 1.0f / lrow[2 * mt + 1];
        const size_t row_lo = (size_t)(b * Sv + i0 + wid * 32 + mt * 16 + r);
#pragma unroll
        for (int nt = 0; nt < 8; ++nt) {
            const int col = h * DKv + nt * 8 + 2 * c;
            *(uint32_t*)(o + row_lo * Dv + col) =
                h2pack(oacc[mt][nt][0] * inv_lo, oacc[mt][nt][1] * inv_lo);
            *(uint32_t*)(o + (row_lo + 8) * Dv + col) =
                h2pack(oacc[mt][nt][2] * inv_hi, oacc[mt][nt][3] * inv_hi);
        }
    }
}

// ---------------------------------------------------------------------------
// LN1: (x fp32 + wo-out fp16 std) -> h fp16 perm16 + h fp32 standard.
// ---------------------------------------------------------------------------
__global__ void __launch_bounds__(256) residual_ln1(
    const float* __restrict__ a, const __half* __restrict__ r,
    const float* __restrict__ g, const float* __restrict__ be,
    __half* __restrict__ outh, float* __restrict__ outf)
{
    const size_t row = (size_t)blockIdx.x * 8 + (threadIdx.x >> 5);
    const int lane = threadIdx.x & 31;

    float v[32];
    float s = 0.f, s2 = 0.f;
#pragma unroll
    for (int gg = 0; gg < 4; ++gg) {
        const int gb = (gg * 32 + lane) * 8;
        const float4 a0 = *(const float4*)(a + row * Dv + gb);
        const float4 a1 = *(const float4*)(a + row * Dv + gb + 4);
        const uint4 ru = *(const uint4*)(r + row * Dv + gb);
        const float2 r0 = __half22float2(*(const __half2*)&ru.x);
        const float2 r1 = __half22float2(*(const __half2*)&ru.y);
        const float2 r2 = __half22float2(*(const __half2*)&ru.z);
        const float2 r3 = __half22float2(*(const __half2*)&ru.w);
        float* vv = v + gg * 8;
        vv[0] = a0.x + r0.x; vv[1] = a0.y + r0.y;
        vv[2] = a0.z + r1.x; vv[3] = a0.w + r1.y;
        vv[4] = a1.x + r2.x; vv[5] = a1.y + r2.y;
        vv[6] = a1.z + r3.x; vv[7] = a1.w + r3.y;
#pragma unroll
        for (int i = 0; i < 8; ++i) { s += vv[i]; s2 += vv[i] * vv[i]; }
    }
#pragma unroll
    for (int o_ = 16; o_ > 0; o_ >>= 1) {
        s  += __shfl_xor_sync(0xffffffffu, s,  o_);
        s2 += __shfl_xor_sync(0xffffffffu, s2, o_);
    }
    const float mu  = s * (1.0f / Dv);
    const float var = s2 * (1.0f / Dv) - mu * mu;
    const float inv = rsqrtf(var + LN_EPS);

#pragma unroll
    for (int gg = 0; gg < 4; ++gg) {
        const int G  = gg * 32 + lane;
        const int gb = G * 8;
        const float4 g0 = *(const float4*)(g + gb);
        const float4 g1v = *(const float4*)(g + gb + 4);
        const float4 b0 = *(const float4*)(be + gb);
        const float4 b1v = *(const float4*)(be + gb + 4);
        const float* vv = v + gg * 8;
        float y[8];
        y[0] = (vv[0] - mu) * inv * g0.x  + b0.x;
        y[1] = (vv[1] - mu) * inv * g0.y  + b0.y;
        y[2] = (vv[2] - mu) * inv * g0.z  + b0.z;
        y[3] = (vv[3] - mu) * inv * g0.w  + b0.w;
        y[4] = (vv[4] - mu) * inv * g1v.x + b1v.x;
        y[5] = (vv[5] - mu) * inv * g1v.y + b1v.y;
        y[6] = (vv[6] - mu) * inv * g1v.z + b1v.z;
        y[7] = (vv[7] - mu) * inv * g1v.w + b1v.w;
        float4 o0, o1;
        o0.x = y[0]; o0.y = y[1]; o0.z = y[2]; o0.w = y[3];
        o1.x = y[4]; o1.y = y[5]; o1.z = y[6]; o1.w = y[7];
        *(float4*)(outf + row * Dv + gb)     = o0;
        *(float4*)(outf + row * Dv + gb + 4) = o1;
        __half* hb = outh + row * Dv + (G >> 1) * 16 + (G & 1) * 2;
        *(uint32_t*)(hb + 0)  = h2pack(y[0], y[1]);
        *(uint32_t*)(hb + 4)  = h2pack(y[2], y[3]);
        *(uint32_t*)(hb + 8)  = h2pack(y[4], y[5]);
        *(uint32_t*)(hb + 12) = h2pack(y[6], y[7]);
    }
}

// LN2: (h fp32 + ff2-out fp16 std) -> out fp32 standard.
__global__ void __launch_bounds__(256) residual_ln2(
    const float* __restrict__ a, const __half* __restrict__ r,
    const float* __restrict__ g, const float* __restrict__ be,
    float* __restrict__ out)
{
    const size_t row = (size_t)blockIdx.x * 8 + (threadIdx.x >> 5);
    const int lane = threadIdx.x & 31;

    float v[32];
    float s = 0.f, s2 = 0.f;
#pragma unroll
    for (int gg = 0; gg < 4; ++gg) {
        const int gb = (gg * 32 + lane) * 8;
        const float4 a0 = *(const float4*)(a + row * Dv + gb);
        const float4 a1 = *(const float4*)(a + row * Dv + gb + 4);
        const uint4 ru = *(const uint4*)(r + row * Dv + gb);
        const float2 r0 = __half22float2(*(const __half2*)&ru.x);
        const float2 r1 = __half22float2(*(const __half2*)&ru.y);
        const float2 r2 = __half22float2(*(const __half2*)&ru.z);
        const float2 r3 = __half22float2(*(const __half2*)&ru.w);
        float* vv = v + gg * 8;
        vv[0] = a0.x + r0.x; vv[1] = a0.y + r0.y;
        vv[2] = a0.z + r1.x; vv[3] = a0.w + r1.y;
        vv[4] = a1.x + r2.x; vv[5] = a1.y + r2.y;
        vv[6] = a1.z + r3.x; vv[7] = a1.w + r3.y;
#pragma unroll
        for (int i = 0; i < 8; ++i) { s += vv[i]; s2 += vv[i] * vv[i]; }
    }
#pragma unroll
    for (int o_ = 16; o_ > 0; o_ >>= 1) {
        s  += __shfl_xor_sync(0xffffffffu, s,  o_);
        s2 += __shfl_xor_sync(0xffffffffu, s2, o_);
    }
    const float mu  = s * (1.0f / Dv);
    const float var = s2 * (1.0f / Dv) - mu * mu;
    const float inv = rsqrtf(var + LN_EPS);

#pragma unroll
    for (int gg = 0; gg < 4; ++gg) {
        const int gb = (gg * 32 + lane) * 8;
        const float4 g0 = *(const float4*)(g + gb);
        const float4 g1v = *(const float4*)(g + gb + 4);
        const float4 b0 = *(const float4*)(be + gb);
        const float4 b1v = *(const float4*)(be + gb + 4);
        const float* vv = v + gg * 8;
        float4 o0, o1;
        o0.x = (vv[0] - mu) * inv * g0.x  + b0.x;
        o0.y = (vv[1] - mu) * inv * g0.y  + b0.y;
        o0.z = (vv[2] - mu) * inv * g0.z  + b0.z;
        o0.w = (vv[3] - mu) * inv * g0.w  + b0.w;
        o1.x = (vv[4] - mu) * inv * g1v.x + b1v.x;
        o1.y = (vv[5] - mu) * inv * g1v.y + b1v.y;
        o1.z = (vv[6] - mu) * inv * g1v.z + b1v.z;
        o1.w = (vv[7] - mu) * inv * g1v.w + b1v.w;
        *(float4*)(out + row * Dv + gb)     = o0;
        *(float4*)(out + row * Dv + gb + 4) = o1;
    }
}

// ---------------------------------------------------------------------------
// Launch
// ---------------------------------------------------------------------------
extern "C" void kernel_launch(void* const* d_in, const int* in_sizes, int n_in,
                              void* d_out, int out_size)
{
    const float* x  = (const float*)d_in[0];
    const float* wq = (const float*)d_in[1];
    const float* bq = (const float*)d_in[2];
    const float* wk = (const float*)d_in[3];
    const float* bk = (const float*)d_in[4];
    const float* wv = (const float*)d_in[5];
    const float* bv = (const float*)d_in[6];
    const float* wo = (const float*)d_in[7];
    const float* bo = (const float*)d_in[8];
    const float* w1 = (const float*)d_in[9];
    const float* b1 = (const float*)d_in[10];
    const float* w2 = (const float*)d_in[11];
    const float* b2 = (const float*)d_in[12];
    const float* g1 = (const float*)d_in[13];
    const float* be1= (const float*)d_in[14];
    const float* g2 = (const float*)d_in[15];
    const float* be2= (const float*)d_in[16];
    float* out = (float*)d_out;

    __half *qkv, *xr, *attn, *hh, *ff1, *vt, *wh, *tmp, *tmp2;
    float *hf, *bqkv;
    cudaGetSymbolAddress((void**)&qkv,  g_qkv);
    cudaGetSymbolAddress((void**)&xr,   g_xr);
    cudaGetSymbolAddress((void**)&attn, g_attn);
    cudaGetSymbolAddress((void**)&hh,   g_h);
    cudaGetSymbolAddress((void**)&hf,   g_hf);
    cudaGetSymbolAddress((void**)&ff1,  g_ff1);
    cudaGetSymbolAddress((void**)&vt,   g_vt);
    cudaGetSymbolAddress((void**)&wh,   g_w);
    cudaGetSymbolAddress((void**)&tmp,  g_tmp);
    cudaGetSymbolAddress((void**)&tmp2, g_tmp2);
    cudaGetSymbolAddress((void**)&bqkv, g_bqkv);

    const size_t MB1 = 1024 * 1024;
    __half* wqkvT = wh;               // [3072][1024]
    __half* woT   = wh + 3 * MB1;
    __half* w1T   = wh + 4 * MB1;     // [F, D]
    __half* w2T   = wh + 8 * MB1;     // [D, F]

    cudaFuncSetAttribute(gemm_h<false, true,  true >,
        cudaFuncAttributeMaxDynamicSharedMemorySize, GSMEM_BYTES);
    cudaFuncSetAttribute(gemm_h<false, false, false>,
        cudaFuncAttributeMaxDynamicSharedMemorySize, GSMEM_BYTES);
    cudaFuncSetAttribute(gemm_h<true,  true,  false>,
        cudaFuncAttributeMaxDynamicSharedMemorySize, GSMEM_BYTES);
    cudaFuncSetAttribute(flash_attn,
        cudaFuncAttributeMaxDynamicSharedMemorySize, FA_SMEM_BYTES);

    // All weight/input prep in ONE launch
    mega_prep<<<MEGA_BLOCKS, 256>>>(wq, wk, wv, wo, w1, w2, x,
                                    bq, bk, bv, wh, xr, bqkv);

    // QKV projection -> qkv fp16 (cols perm16, q pre-scaled)
    gemm_h<false, true, true><<<dim3(QS / 128, Mv / 128), 128, GSMEM_BYTES>>>(
        Dv, QS, xr, wqkvT, bqkv, qkv);

    // V transpose for fp16 PV fragments
    dim3 tb(32, 8);
    transpose_v<<<dim3(Sv / 64, Dv / 64, Bv), tb>>>(qkv, vt);

    // Flash attention -> attn fp16 (dperm); register P
    flash_attn<<<dim3(Sv / 128, Bv * Hv), 128, FA_SMEM_BYTES>>>(qkv, vt, attn);

    const dim3 gDD(Dv / 128, Mv / 128);   // (8, 32)
    const dim3 gDF(Fv / 128, Mv / 128);   // (32, 32)

    // Output projection (fp16 standard) + LN1 (dual output)
    gemm_h<false, false, false><<<gDD, 128, GSMEM_BYTES>>>(Dv, Dv, attn, woT, bo, tmp);
    residual_ln1<<<Mv / 8, 256>>>(x, tmp, g1, be1, hh, hf);

    // FFN + LN2
    gemm_h<true,  true,  false><<<gDF, 128, GSMEM_BYTES>>>(Dv, Fv, hh, w1T, b1, ff1);
    gemm_h<false, false, false><<<gDD, 128, GSMEM_BYTES>>>(Fv, Dv, ff1, w2T, b2, tmp2);
    residual_ln2<<<Mv / 8, 256>>>(hf, tmp2, g2, be2, out);
}